// round 2
// baseline (speedup 1.0000x reference)
#include <cuda_runtime.h>
#include <cuda_bf16.h>

// ---------------- problem constants ----------------
#define BB 8
#define SS 1024
#define DD 512
#define HH 8
#define DKK 64
#define DVV 64
#define DFFF 2048
#define SD (SS*DD)          // 524288 = 2^19
#define NEGV (-1e10f)

// ---------------- scratch (device globals; no allocation allowed) ----------------
__device__ float g_q [BB*HH*SS*DKK];      // 16MB
__device__ float g_k [BB*HH*SS*DKK];
__device__ float g_v [BB*HH*SS*DVV];
__device__ float g_sc[(size_t)BB*HH*SS*SS]; // 256MB
__device__ float g_cat[BB*SS*HH*DVV];     // 16MB
__device__ float g_z [BB*SS*DD];
__device__ float g_x1[BB*SS*DD];
__device__ float g_x2[BB*SS*DD];
__device__ float g_ff[BB*SS*DFFF];        // 64MB
__device__ float2 g_part[BB*128];
__device__ float2 g_stats[BB];

// ---------------- generic batched SGEMM ----------------
// C[bz] = alpha * A[bz] * B[bz] (+ bias[n]) (+ res) (ReLU optional)
// TRANSB: B stored [N,K] row-major (C = A * B^T); else B is [K,N].
#define BM 64
#define BN 64
#define BKT 16

template<bool TRANSB, bool RELU>
__global__ void __launch_bounds__(256) sgemm(
    const float* __restrict__ A, const float* __restrict__ Bm,
    const float* __restrict__ bias, const float* __restrict__ res,
    float* __restrict__ C,
    int M, int N, int K, int lda, int ldb, int ldc,
    int divA, long long strideA,
    int modB, long long strideB,
    int modBias, long long strideBias,
    int divC, long long strideC1, int modC, long long strideC2,
    float alpha)
{
    __shared__ float As[BKT][BM];
    __shared__ float Bs[BKT][BN];

    const int bz = blockIdx.z;
    A  += (long long)(bz / divA) * strideA;
    Bm += (long long)(bz % modB) * strideB;
    const long long coff = (long long)(bz / divC) * strideC1 + (long long)(bz % modC) * strideC2;
    C += coff;
    if (res) res += coff;
    const float* bptr = bias ? (bias + (long long)(bz % modBias) * strideBias) : nullptr;

    const int tid = threadIdx.x;
    const int tx = tid & 15;
    const int ty = tid >> 4;
    const int row0 = blockIdx.y * BM;
    const int col0 = blockIdx.x * BN;

    float acc[4][4] = {};

    for (int k0 = 0; k0 < K; k0 += BKT) {
        #pragma unroll
        for (int i = tid; i < BM*BKT; i += 256) {
            int r = i >> 4, c = i & 15;
            As[c][r] = A[(long long)(row0 + r) * lda + (k0 + c)];
        }
        if (TRANSB) {
            #pragma unroll
            for (int i = tid; i < BKT*BN; i += 256) {
                int n = i >> 4, c = i & 15;
                Bs[c][n] = Bm[(long long)(col0 + n) * ldb + (k0 + c)];
            }
        } else {
            #pragma unroll
            for (int i = tid; i < BKT*BN; i += 256) {
                int c = i >> 6, n = i & 63;
                Bs[c][n] = Bm[(long long)(k0 + c) * ldb + (col0 + n)];
            }
        }
        __syncthreads();
        #pragma unroll
        for (int k = 0; k < BKT; k++) {
            float4 av = *(const float4*)&As[k][ty*4];
            float4 bv = *(const float4*)&Bs[k][tx*4];
            float a[4] = {av.x, av.y, av.z, av.w};
            float b[4] = {bv.x, bv.y, bv.z, bv.w};
            #pragma unroll
            for (int i = 0; i < 4; i++)
                #pragma unroll
                for (int j = 0; j < 4; j++)
                    acc[i][j] += a[i] * b[j];
        }
        __syncthreads();
    }

    #pragma unroll
    for (int i = 0; i < 4; i++) {
        int r = row0 + ty*4 + i;
        #pragma unroll
        for (int j = 0; j < 4; j++) {
            int cn = col0 + tx*4 + j;
            float vv = acc[i][j] * alpha;
            if (bptr) vv += bptr[cn];
            if (res)  vv += res[(long long)r * ldc + cn];
            if (RELU) vv = fmaxf(vv, 0.f);
            C[(long long)r * ldc + cn] = vv;
        }
    }
}

// ---------------- masked softmax over key dim (row = 1024) ----------------
__global__ void __launch_bounds__(256) softmax_mask_kernel(
    float* __restrict__ sc, const int* __restrict__ mask, int HS)
{
    const long long row = blockIdx.x;
    const int b = (int)(row / HS);
    float4* p = (float4*)sc + row * 256;
    const int4* mrow = (const int4*)(mask + b * SS);
    const int t = threadIdx.x;

    float4 v = p[t];
    int4 m = mrow[t];
    v.x = m.x ? v.x : NEGV;
    v.y = m.y ? v.y : NEGV;
    v.z = m.z ? v.z : NEGV;
    v.w = m.w ? v.w : NEGV;

    __shared__ float smx[8];
    __shared__ float ssm[8];
    const int lane = t & 31, w = t >> 5;

    float mx = fmaxf(fmaxf(v.x, v.y), fmaxf(v.z, v.w));
    #pragma unroll
    for (int o = 16; o; o >>= 1) mx = fmaxf(mx, __shfl_xor_sync(0xffffffffu, mx, o));
    if (lane == 0) smx[w] = mx;
    __syncthreads();
    float bm = smx[0];
    #pragma unroll
    for (int j = 1; j < 8; j++) bm = fmaxf(bm, smx[j]);

    float4 e;
    e.x = __expf(v.x - bm);
    e.y = __expf(v.y - bm);
    e.z = __expf(v.z - bm);
    e.w = __expf(v.w - bm);
    float s = e.x + e.y + e.z + e.w;
    #pragma unroll
    for (int o = 16; o; o >>= 1) s += __shfl_xor_sync(0xffffffffu, s, o);
    if (lane == 0) ssm[w] = s;
    __syncthreads();
    float tot = 0.f;
    #pragma unroll
    for (int j = 0; j < 8; j++) tot += ssm[j];
    float inv = 1.f / tot;
    e.x *= inv; e.y *= inv; e.z *= inv; e.w *= inv;
    p[t] = e;
}

// ---------------- LayerNorm over whole [S,D] per batch ----------------
__global__ void __launch_bounds__(256) ln_partial_kernel(
    const float* __restrict__ z, float2* __restrict__ part)
{
    const long long base = (long long)blockIdx.x * 4096;
    const float4* p = (const float4*)(z + base);
    float s = 0.f, q = 0.f;
    for (int i = threadIdx.x; i < 1024; i += 256) {
        float4 v = p[i];
        s += v.x + v.y + v.z + v.w;
        q += v.x*v.x + v.y*v.y + v.z*v.z + v.w*v.w;
    }
    __shared__ float ss[8], sq[8];
    const int lane = threadIdx.x & 31, w = threadIdx.x >> 5;
    #pragma unroll
    for (int o = 16; o; o >>= 1) {
        s += __shfl_xor_sync(0xffffffffu, s, o);
        q += __shfl_xor_sync(0xffffffffu, q, o);
    }
    if (lane == 0) { ss[w] = s; sq[w] = q; }
    __syncthreads();
    if (threadIdx.x == 0) {
        float ts = 0.f, tq = 0.f;
        #pragma unroll
        for (int j = 0; j < 8; j++) { ts += ss[j]; tq += sq[j]; }
        part[blockIdx.x] = make_float2(ts, tq);
    }
}

__global__ void __launch_bounds__(128) ln_final_kernel(
    const float2* __restrict__ part, float2* __restrict__ stats)
{
    float2 v = part[blockIdx.x * 128 + threadIdx.x];
    float s = v.x, q = v.y;
    __shared__ float ss[4], sq[4];
    const int lane = threadIdx.x & 31, w = threadIdx.x >> 5;
    #pragma unroll
    for (int o = 16; o; o >>= 1) {
        s += __shfl_xor_sync(0xffffffffu, s, o);
        q += __shfl_xor_sync(0xffffffffu, q, o);
    }
    if (lane == 0) { ss[w] = s; sq[w] = q; }
    __syncthreads();
    if (threadIdx.x == 0) {
        float ts = 0.f, tq = 0.f;
        #pragma unroll
        for (int j = 0; j < 4; j++) { ts += ss[j]; tq += sq[j]; }
        float mean = ts * (1.f / SD);
        float var = tq * (1.f / SD) - mean * mean;
        stats[blockIdx.x] = make_float2(mean, rsqrtf(var + 1e-6f));
    }
}

__global__ void __launch_bounds__(256) ln_apply_kernel(
    const float* __restrict__ z, const float2* __restrict__ stats,
    const float* __restrict__ w, const float* __restrict__ bias,
    float* __restrict__ out)
{
    const int idx = blockIdx.x * 256 + threadIdx.x;          // one float4 each; grid covers exactly B*S*D/4
    const long long linear = (long long)idx * 4;
    const int b = (int)(linear >> 19);                        // S*D = 2^19
    const int sd = (int)(linear & (SD - 1));
    float2 st = stats[b];
    float4 v  = ((const float4*)z)[idx];
    float4 wv = ((const float4*)w)[sd >> 2];
    float4 bv = ((const float4*)bias)[sd >> 2];
    float4 o;
    o.x = (v.x - st.x) * st.y * wv.x + bv.x;
    o.y = (v.y - st.x) * st.y * wv.y + bv.y;
    o.z = (v.z - st.x) * st.y * wv.z + bv.z;
    o.w = (v.w - st.x) * st.y * wv.w + bv.w;
    ((float4*)out)[idx] = o;
}

// ---------------- host orchestration ----------------
static void run_mha(const float* qin, const float* kvin,
                    const float* wq, const float* bq,
                    const float* wk, const float* bk,
                    const float* wv, const float* bv,
                    const float* wo, const float* bo,
                    const int* mask,
                    const float* resid,
                    float* q, float* k, float* v, float* sc, float* cat, float* zout)
{
    // head projections: [S,D] @ [D,DK] per (b,h)
    dim3 gp(1, SS/BM, BB*HH);
    sgemm<false,false><<<gp,256>>>(qin,  wq, bq, nullptr, q, SS, DKK, DD, DD, DKK, DKK,
        HH, (long long)SD, HH, (long long)DD*DKK, HH, DKK, 1, (long long)SS*DKK, 1, 0, 1.f);
    sgemm<false,false><<<gp,256>>>(kvin, wk, bk, nullptr, k, SS, DKK, DD, DD, DKK, DKK,
        HH, (long long)SD, HH, (long long)DD*DKK, HH, DKK, 1, (long long)SS*DKK, 1, 0, 1.f);
    sgemm<false,false><<<gp,256>>>(kvin, wv, bv, nullptr, v, SS, DVV, DD, DD, DVV, DVV,
        HH, (long long)SD, HH, (long long)DD*DVV, HH, DVV, 1, (long long)SS*DVV, 1, 0, 1.f);
    // scores = (q @ k^T) / 8
    dim3 gs(SS/BN, SS/BM, BB*HH);
    sgemm<true,false><<<gs,256>>>(q, k, nullptr, nullptr, sc, SS, SS, DKK, DKK, DKK, SS,
        1, (long long)SS*DKK, BB*HH, (long long)SS*DKK, 1, 0, 1, (long long)SS*SS, 1, 0, 0.125f);
    // masked softmax
    softmax_mask_kernel<<<BB*HH*SS, 256>>>(sc, mask, HH*SS);
    // o = a @ v, written directly in concat [B,S,H*DV] layout
    dim3 ga(1, SS/BM, BB*HH);
    sgemm<false,false><<<ga,256>>>(sc, v, nullptr, nullptr, cat, SS, DVV, SS, SS, DVV, HH*DVV,
        1, (long long)SS*SS, BB*HH, (long long)SS*DVV, 1, 0,
        HH, (long long)SS*HH*DVV, HH, (long long)DVV, 1.f);
    // out projection + bias + residual
    dim3 go(DD/BN, SS/BM, BB);
    sgemm<true,false><<<go,256>>>(cat, wo, bo, resid, zout, SS, DD, HH*DVV, HH*DVV, HH*DVV, DD,
        1, (long long)SS*HH*DVV, 1, 0, 1, 0, 1, (long long)SD, 1, 0, 1.f);
}

static void run_ln(const float* z, const float* w, const float* b, float* out,
                   float2* part, float2* stats)
{
    ln_partial_kernel<<<BB*128, 256>>>(z, part);
    ln_final_kernel<<<BB, 128>>>(part, stats);
    ln_apply_kernel<<<(BB*SD)/(256*4), 256>>>(z, stats, w, b, out);
}

extern "C" void kernel_launch(void* const* d_in, const int* in_sizes, int n_in,
                              void* d_out, int out_size)
{
    const float* x        = (const float*)d_in[0];
    const float* y        = (const float*)d_in[1];
    const int*   src_mask = (const int*)  d_in[2];
    const int*   trg_mask = (const int*)  d_in[3];
    const float* m1_wq = (const float*)d_in[4];
    const float* m1_bq = (const float*)d_in[5];
    const float* m1_wk = (const float*)d_in[6];
    const float* m1_bk = (const float*)d_in[7];
    const float* m1_wv = (const float*)d_in[8];
    const float* m1_bv = (const float*)d_in[9];
    const float* m1_wo = (const float*)d_in[10];
    const float* m1_bo = (const float*)d_in[11];
    const float* m2_wq = (const float*)d_in[12];
    const float* m2_bq = (const float*)d_in[13];
    const float* m2_wk = (const float*)d_in[14];
    const float* m2_bk = (const float*)d_in[15];
    const float* m2_wv = (const float*)d_in[16];
    const float* m2_bv = (const float*)d_in[17];
    const float* m2_wo = (const float*)d_in[18];
    const float* m2_bo = (const float*)d_in[19];
    const float* pw1   = (const float*)d_in[20];
    const float* pb1   = (const float*)d_in[21];
    const float* pw2   = (const float*)d_in[22];
    const float* pb2   = (const float*)d_in[23];
    const float* ln1_w = (const float*)d_in[24];
    const float* ln1_b = (const float*)d_in[25];
    const float* ln2_w = (const float*)d_in[26];
    const float* ln2_b = (const float*)d_in[27];
    const float* ln3_w = (const float*)d_in[28];
    const float* ln3_b = (const float*)d_in[29];
    float* out = (float*)d_out;

    float *q, *k, *v, *sc, *cat, *z, *x1, *x2, *ff;
    float2 *part, *stats;
    cudaGetSymbolAddress((void**)&q,   g_q);
    cudaGetSymbolAddress((void**)&k,   g_k);
    cudaGetSymbolAddress((void**)&v,   g_v);
    cudaGetSymbolAddress((void**)&sc,  g_sc);
    cudaGetSymbolAddress((void**)&cat, g_cat);
    cudaGetSymbolAddress((void**)&z,   g_z);
    cudaGetSymbolAddress((void**)&x1,  g_x1);
    cudaGetSymbolAddress((void**)&x2,  g_x2);
    cudaGetSymbolAddress((void**)&ff,  g_ff);
    cudaGetSymbolAddress((void**)&part,  g_part);
    cudaGetSymbolAddress((void**)&stats, g_stats);

    // 1) self-attention (mask = trg_mask) + residual, then LN1 -> x1
    run_mha(x, x, m1_wq, m1_bq, m1_wk, m1_bk, m1_wv, m1_bv, m1_wo, m1_bo,
            trg_mask, x, q, k, v, sc, cat, z);
    run_ln(z, ln1_w, ln1_b, x1, part, stats);

    // 2) cross-attention (q from x1, k/v from y; mask = src_mask) + residual, LN2 -> x2
    run_mha(x1, y, m2_wq, m2_bq, m2_wk, m2_bk, m2_wv, m2_bv, m2_wo, m2_bo,
            src_mask, x1, q, k, v, sc, cat, z);
    run_ln(z, ln2_w, ln2_b, x2, part, stats);

    // 3) FFN: relu(x2 @ pw1^T + pb1) @ pw2^T + pb2 + x2, then LN3 -> out
    dim3 gf1(DFFF/BN, SS/BM, BB);
    sgemm<true,true><<<gf1,256>>>(x2, pw1, pb1, nullptr, ff, SS, DFFF, DD, DD, DD, DFFF,
        1, (long long)SD, 1, 0, 1, 0, 1, (long long)SS*DFFF, 1, 0, 1.f);
    dim3 gf2(DD/BN, SS/BM, BB);
    sgemm<true,false><<<gf2,256>>>(ff, pw2, pb2, x2, z, SS, DD, DFFF, DFFF, DFFF, DD,
        1, (long long)SS*DFFF, 1, 0, 1, 0, 1, (long long)SD, 1, 0, 1.f);
    run_ln(z, ln3_w, ln3_b, out, part, stats);
}

// round 3
// speedup vs baseline: 1.4992x; 1.4992x over previous
#include <cuda_runtime.h>
#include <cuda_bf16.h>

// ---------------- problem constants ----------------
#define BB 8
#define SS 1024
#define DD 512
#define HH 8
#define DKK 64
#define DVV 64
#define DFFF 2048
#define SD (SS*DD)          // 524288 = 2^19
#define NEGV (-1e10f)

// ---------------- scratch (device globals; no allocation allowed) ----------------
__device__ float g_q [BB*SS*DD];            // packed [B,S,H*DK]
__device__ float g_k [BB*SS*DD];
__device__ float g_v [BB*SS*DD];
__device__ float g_sc[(size_t)BB*HH*SS*SS]; // 256MB
__device__ float g_cat[BB*SS*HH*DVV];
__device__ float g_z [BB*SS*DD];
__device__ float g_x1[BB*SS*DD];
__device__ float g_x2[BB*SS*DD];
__device__ float g_ff[BB*SS*DFFF];
__device__ float g_wpq[DD*HH*DKK];          // packed weights [D, H*DK]
__device__ float g_wpk[DD*HH*DKK];
__device__ float g_wpv[DD*HH*DVV];
__device__ float2 g_part[BB*128];
__device__ float2 g_stats[BB];

// ---------------- weight repack: [H,D,DK] -> [D, H*DK] ----------------
__global__ void __launch_bounds__(256) repack_w(
    const float* __restrict__ w, float* __restrict__ out)
{
    int idx = blockIdx.x * 256 + threadIdx.x;   // over H*D*DK = 2^18
    int j = idx & 63;             // dk
    int d = (idx >> 6) & 511;     // d
    int h = idx >> 15;            // h
    out[d * (HH*DKK) + h * DKK + j] = w[idx];
}

// ---------------- high-intensity batched SGEMM ----------------
// C = alpha*A*B (+bias) (+res) (mask -> NEGV) (ReLU), BK=8, 256 threads.
// TRANSB: B stored [N,K] row-major. Batch offsets: (bz/div)*s1 + (bz%mod)*s2.
template<int BM_, int BN_, int TM_, int TN_, bool TRANSB, bool RELU, bool MASKED>
__global__ void __launch_bounds__(256) gemm2(
    const float* __restrict__ A, const float* __restrict__ Bm,
    const float* __restrict__ bias, const float* __restrict__ res,
    const int* __restrict__ maskp, float* __restrict__ C,
    int K, int lda, int ldb, int ldc,
    int divA, long long sA1, int modA, long long sA2,
    int divB, long long sB1, int modB, long long sB2,
    int divC, long long sC1, int modC, long long sC2,
    int maskDiv, float alpha)
{
    constexpr int BK = 8;
    __shared__ float As[BK][BM_];
    __shared__ float Bs[BK][BN_];

    const int bz = blockIdx.z;
    A  += (long long)(bz / divA) * sA1 + (long long)(bz % modA) * sA2;
    Bm += (long long)(bz / divB) * sB1 + (long long)(bz % modB) * sB2;
    const long long coff = (long long)(bz / divC) * sC1 + (long long)(bz % modC) * sC2;
    C += coff;
    if (res) res += coff;
    const int* mrow = MASKED ? (maskp + (long long)(bz / maskDiv) * SS) : nullptr;

    const int tid = threadIdx.x;
    constexpr int NX = BN_ / TN_;
    const int tx = tid % NX;
    const int ty = tid / NX;
    const int row0 = blockIdx.y * BM_;
    const int col0 = blockIdx.x * BN_;

    float acc[TM_][TN_] = {};
    float ar[TM_], br[TN_];

    constexpr int A_F4 = BM_ * BK / 4;                  // float4s in A tile
    constexpr int A_PER = (A_F4 + 255) / 256;
    constexpr int B_F4 = BN_ * BK / 4;
    constexpr int B_PER = (B_F4 + 255) / 256;

    for (int k0 = 0; k0 < K; k0 += BK) {
        #pragma unroll
        for (int t = 0; t < A_PER; t++) {
            int idx = tid + t * 256;
            if ((A_F4 & 255) == 0 || idx < A_F4) {
                int r = idx >> 1, c4 = (idx & 1) * 4;
                float4 v = *(const float4*)&A[(long long)(row0 + r) * lda + k0 + c4];
                As[c4+0][r] = v.x; As[c4+1][r] = v.y; As[c4+2][r] = v.z; As[c4+3][r] = v.w;
            }
        }
        if (TRANSB) {
            #pragma unroll
            for (int t = 0; t < B_PER; t++) {
                int idx = tid + t * 256;
                if ((B_F4 & 255) == 0 || idx < B_F4) {
                    int r = idx >> 1, c4 = (idx & 1) * 4;
                    float4 v = *(const float4*)&Bm[(long long)(col0 + r) * ldb + k0 + c4];
                    Bs[c4+0][r] = v.x; Bs[c4+1][r] = v.y; Bs[c4+2][r] = v.z; Bs[c4+3][r] = v.w;
                }
            }
        } else {
            #pragma unroll
            for (int t = 0; t < B_PER; t++) {
                int idx = tid + t * 256;
                if ((B_F4 & 255) == 0 || idx < B_F4) {
                    constexpr int RW = BN_ / 4;
                    int r = idx / RW, c = idx % RW;
                    *(float4*)&Bs[r][c * 4] =
                        *(const float4*)&Bm[(long long)(k0 + r) * ldb + col0 + c * 4];
                }
            }
        }
        __syncthreads();

        #pragma unroll
        for (int kk = 0; kk < BK; kk++) {
            #pragma unroll
            for (int i = 0; i < TM_; i += 4)
                *(float4*)&ar[i] = *(const float4*)&As[kk][ty * TM_ + i];
            #pragma unroll
            for (int j = 0; j < TN_; j += 4)
                *(float4*)&br[j] = *(const float4*)&Bs[kk][tx * TN_ + j];
            #pragma unroll
            for (int i = 0; i < TM_; i++)
                #pragma unroll
                for (int j = 0; j < TN_; j++)
                    acc[i][j] += ar[i] * br[j];
        }
        __syncthreads();
    }

    // vectorized epilogue
    #pragma unroll
    for (int i = 0; i < TM_; i++) {
        const long long r = row0 + ty * TM_ + i;
        #pragma unroll
        for (int jq = 0; jq < TN_; jq += 4) {
            const int cn = col0 + tx * TN_ + jq;
            float4 o;
            o.x = acc[i][jq+0] * alpha;
            o.y = acc[i][jq+1] * alpha;
            o.z = acc[i][jq+2] * alpha;
            o.w = acc[i][jq+3] * alpha;
            if (bias) {
                float4 bv = *(const float4*)&bias[cn];
                o.x += bv.x; o.y += bv.y; o.z += bv.z; o.w += bv.w;
            }
            if (res) {
                float4 rv = *(const float4*)&res[r * ldc + cn];
                o.x += rv.x; o.y += rv.y; o.z += rv.z; o.w += rv.w;
            }
            if (MASKED) {
                int4 m = *(const int4*)&mrow[cn];
                if (m.x == 0) o.x = NEGV;
                if (m.y == 0) o.y = NEGV;
                if (m.z == 0) o.z = NEGV;
                if (m.w == 0) o.w = NEGV;
            }
            if (RELU) {
                o.x = fmaxf(o.x, 0.f); o.y = fmaxf(o.y, 0.f);
                o.z = fmaxf(o.z, 0.f); o.w = fmaxf(o.w, 0.f);
            }
            *(float4*)&C[r * ldc + cn] = o;
        }
    }
}

// ---------------- softmax over key dim (mask already applied in GEMM) ----------------
__global__ void __launch_bounds__(256) softmax_kernel(float* __restrict__ sc)
{
    const long long row = blockIdx.x;
    float4* p = (float4*)sc + row * 256;
    const int t = threadIdx.x;

    float4 v = p[t];

    __shared__ float smx[8];
    __shared__ float ssm[8];
    const int lane = t & 31, w = t >> 5;

    float mx = fmaxf(fmaxf(v.x, v.y), fmaxf(v.z, v.w));
    #pragma unroll
    for (int o = 16; o; o >>= 1) mx = fmaxf(mx, __shfl_xor_sync(0xffffffffu, mx, o));
    if (lane == 0) smx[w] = mx;
    __syncthreads();
    float bm = smx[0];
    #pragma unroll
    for (int j = 1; j < 8; j++) bm = fmaxf(bm, smx[j]);

    float4 e;
    e.x = __expf(v.x - bm);
    e.y = __expf(v.y - bm);
    e.z = __expf(v.z - bm);
    e.w = __expf(v.w - bm);
    float s = e.x + e.y + e.z + e.w;
    #pragma unroll
    for (int o = 16; o; o >>= 1) s += __shfl_xor_sync(0xffffffffu, s, o);
    if (lane == 0) ssm[w] = s;
    __syncthreads();
    float tot = 0.f;
    #pragma unroll
    for (int j = 0; j < 8; j++) tot += ssm[j];
    float inv = 1.f / tot;
    e.x *= inv; e.y *= inv; e.z *= inv; e.w *= inv;
    p[t] = e;
}

// ---------------- LayerNorm over whole [S,D] per batch ----------------
__global__ void __launch_bounds__(256) ln_partial_kernel(
    const float* __restrict__ z, float2* __restrict__ part)
{
    const long long base = (long long)blockIdx.x * 4096;
    const float4* p = (const float4*)(z + base);
    float s = 0.f, q = 0.f;
    for (int i = threadIdx.x; i < 1024; i += 256) {
        float4 v = p[i];
        s += v.x + v.y + v.z + v.w;
        q += v.x*v.x + v.y*v.y + v.z*v.z + v.w*v.w;
    }
    __shared__ float ss[8], sq[8];
    const int lane = threadIdx.x & 31, w = threadIdx.x >> 5;
    #pragma unroll
    for (int o = 16; o; o >>= 1) {
        s += __shfl_xor_sync(0xffffffffu, s, o);
        q += __shfl_xor_sync(0xffffffffu, q, o);
    }
    if (lane == 0) { ss[w] = s; sq[w] = q; }
    __syncthreads();
    if (threadIdx.x == 0) {
        float ts = 0.f, tq = 0.f;
        #pragma unroll
        for (int j = 0; j < 8; j++) { ts += ss[j]; tq += sq[j]; }
        part[blockIdx.x] = make_float2(ts, tq);
    }
}

__global__ void __launch_bounds__(128) ln_final_kernel(
    const float2* __restrict__ part, float2* __restrict__ stats)
{
    float2 v = part[blockIdx.x * 128 + threadIdx.x];
    float s = v.x, q = v.y;
    __shared__ float ss[4], sq[4];
    const int lane = threadIdx.x & 31, w = threadIdx.x >> 5;
    #pragma unroll
    for (int o = 16; o; o >>= 1) {
        s += __shfl_xor_sync(0xffffffffu, s, o);
        q += __shfl_xor_sync(0xffffffffu, q, o);
    }
    if (lane == 0) { ss[w] = s; sq[w] = q; }
    __syncthreads();
    if (threadIdx.x == 0) {
        float ts = 0.f, tq = 0.f;
        #pragma unroll
        for (int j = 0; j < 4; j++) { ts += ss[j]; tq += sq[j]; }
        float mean = ts * (1.f / SD);
        float var = tq * (1.f / SD) - mean * mean;
        stats[blockIdx.x] = make_float2(mean, rsqrtf(var + 1e-6f));
    }
}

__global__ void __launch_bounds__(256) ln_apply_kernel(
    const float* __restrict__ z, const float2* __restrict__ stats,
    const float* __restrict__ w, const float* __restrict__ bias,
    float* __restrict__ out)
{
    const int idx = blockIdx.x * 256 + threadIdx.x;
    const long long linear = (long long)idx * 4;
    const int b = (int)(linear >> 19);
    const int sd = (int)(linear & (SD - 1));
    float2 st = stats[b];
    float4 v  = ((const float4*)z)[idx];
    float4 wv = ((const float4*)w)[sd >> 2];
    float4 bv = ((const float4*)bias)[sd >> 2];
    float4 o;
    o.x = (v.x - st.x) * st.y * wv.x + bv.x;
    o.y = (v.y - st.x) * st.y * wv.y + bv.y;
    o.z = (v.z - st.x) * st.y * wv.z + bv.z;
    o.w = (v.w - st.x) * st.y * wv.w + bv.w;
    ((float4*)out)[idx] = o;
}

// ---------------- host orchestration ----------------
static void run_mha2(const float* qin, const float* kvin,
                     const float* wq, const float* bq,
                     const float* wk, const float* bk,
                     const float* wv, const float* bv,
                     const float* wo, const float* bo,
                     const int* mask, const float* resid,
                     float* wpq, float* wpk, float* wpv,
                     float* q, float* k, float* v,
                     float* sc, float* cat, float* zout)
{
    repack_w<<<1024, 256>>>(wq, wpq);
    repack_w<<<1024, 256>>>(wk, wpk);
    repack_w<<<1024, 256>>>(wv, wpv);

    // projections: [B*S,512] @ [512,512] -> packed q/k/v [B,S,H*64]
    dim3 gp(512/128, (BB*SS)/128, 1);
    gemm2<128,128,8,8,false,false,false><<<gp,256>>>(qin,  wpq, bq, nullptr, nullptr, q,
        DD, DD, DD, DD, 1,0,1,0, 1,0,1,0, 1,0,1,0, 1, 1.f);
    gemm2<128,128,8,8,false,false,false><<<gp,256>>>(kvin, wpk, bk, nullptr, nullptr, k,
        DD, DD, DD, DD, 1,0,1,0, 1,0,1,0, 1,0,1,0, 1, 1.f);
    gemm2<128,128,8,8,false,false,false><<<gp,256>>>(kvin, wpv, bv, nullptr, nullptr, v,
        DD, DD, DD, DD, 1,0,1,0, 1,0,1,0, 1,0,1,0, 1, 1.f);

    // scores = (q @ k^T)/8, mask fused; per (b,h): strided views of packed q/k
    dim3 gs(SS/128, SS/128, BB*HH);
    gemm2<128,128,8,8,true,false,true><<<gs,256>>>(q, k, nullptr, nullptr, mask, sc,
        DKK, DD, DD, SS,
        HH, (long long)SS*DD, HH, DKK,
        HH, (long long)SS*DD, HH, DKK,
        1, (long long)SS*SS, 1, 0,
        HH, 0.125f);

    softmax_kernel<<<BB*HH*SS, 256>>>(sc);

    // AV: [S,S] @ [S,64] -> cat [B,S,H*64]
    dim3 ga(1, SS/256, BB*HH);
    gemm2<256,64,8,8,false,false,false><<<ga,256>>>(sc, v, nullptr, nullptr, nullptr, cat,
        SS, SS, DD, DD,
        1, (long long)SS*SS, 1, 0,
        HH, (long long)SS*DD, HH, DKK,
        HH, (long long)SS*DD, HH, DKK,
        1, 1.f);

    // out projection + bias + residual
    dim3 go(512/128, (BB*SS)/128, 1);
    gemm2<128,128,8,8,true,false,false><<<go,256>>>(cat, wo, bo, resid, nullptr, zout,
        DD, DD, DD, DD, 1,0,1,0, 1,0,1,0, 1,0,1,0, 1, 1.f);
}

static void run_ln(const float* z, const float* w, const float* b, float* out,
                   float2* part, float2* stats)
{
    ln_partial_kernel<<<BB*128, 256>>>(z, part);
    ln_final_kernel<<<BB, 128>>>(part, stats);
    ln_apply_kernel<<<(BB*SD)/(256*4), 256>>>(z, stats, w, b, out);
}

extern "C" void kernel_launch(void* const* d_in, const int* in_sizes, int n_in,
                              void* d_out, int out_size)
{
    const float* x        = (const float*)d_in[0];
    const float* y        = (const float*)d_in[1];
    const int*   src_mask = (const int*)  d_in[2];
    const int*   trg_mask = (const int*)  d_in[3];
    const float* m1_wq = (const float*)d_in[4];
    const float* m1_bq = (const float*)d_in[5];
    const float* m1_wk = (const float*)d_in[6];
    const float* m1_bk = (const float*)d_in[7];
    const float* m1_wv = (const float*)d_in[8];
    const float* m1_bv = (const float*)d_in[9];
    const float* m1_wo = (const float*)d_in[10];
    const float* m1_bo = (const float*)d_in[11];
    const float* m2_wq = (const float*)d_in[12];
    const float* m2_bq = (const float*)d_in[13];
    const float* m2_wk = (const float*)d_in[14];
    const float* m2_bk = (const float*)d_in[15];
    const float* m2_wv = (const float*)d_in[16];
    const float* m2_bv = (const float*)d_in[17];
    const float* m2_wo = (const float*)d_in[18];
    const float* m2_bo = (const float*)d_in[19];
    const float* pw1   = (const float*)d_in[20];
    const float* pb1   = (const float*)d_in[21];
    const float* pw2   = (const float*)d_in[22];
    const float* pb2   = (const float*)d_in[23];
    const float* ln1_w = (const float*)d_in[24];
    const float* ln1_b = (const float*)d_in[25];
    const float* ln2_w = (const float*)d_in[26];
    const float* ln2_b = (const float*)d_in[27];
    const float* ln3_w = (const float*)d_in[28];
    const float* ln3_b = (const float*)d_in[29];
    float* out = (float*)d_out;

    float *q, *k, *v, *sc, *cat, *z, *x1, *x2, *ff, *wpq, *wpk, *wpv;
    float2 *part, *stats;
    cudaGetSymbolAddress((void**)&q,   g_q);
    cudaGetSymbolAddress((void**)&k,   g_k);
    cudaGetSymbolAddress((void**)&v,   g_v);
    cudaGetSymbolAddress((void**)&sc,  g_sc);
    cudaGetSymbolAddress((void**)&cat, g_cat);
    cudaGetSymbolAddress((void**)&z,   g_z);
    cudaGetSymbolAddress((void**)&x1,  g_x1);
    cudaGetSymbolAddress((void**)&x2,  g_x2);
    cudaGetSymbolAddress((void**)&ff,  g_ff);
    cudaGetSymbolAddress((void**)&wpq, g_wpq);
    cudaGetSymbolAddress((void**)&wpk, g_wpk);
    cudaGetSymbolAddress((void**)&wpv, g_wpv);
    cudaGetSymbolAddress((void**)&part,  g_part);
    cudaGetSymbolAddress((void**)&stats, g_stats);

    // 1) self-attention (trg_mask) + residual, LN1 -> x1
    run_mha2(x, x, m1_wq, m1_bq, m1_wk, m1_bk, m1_wv, m1_bv, m1_wo, m1_bo,
             trg_mask, x, wpq, wpk, wpv, q, k, v, sc, cat, z);
    run_ln(z, ln1_w, ln1_b, x1, part, stats);

    // 2) cross-attention (q from x1, k/v from y; src_mask) + residual, LN2 -> x2
    run_mha2(x1, y, m2_wq, m2_bq, m2_wk, m2_bk, m2_wv, m2_bv, m2_wo, m2_bo,
             src_mask, x1, wpq, wpk, wpv, q, k, v, sc, cat, z);
    run_ln(z, ln2_w, ln2_b, x2, part, stats);

    // 3) FFN + residual, LN3 -> out
    dim3 gf1(DFFF/128, (BB*SS)/128, 1);
    gemm2<128,128,8,8,true,true,false><<<gf1,256>>>(x2, pw1, pb1, nullptr, nullptr, ff,
        DD, DD, DD, DFFF, 1,0,1,0, 1,0,1,0, 1,0,1,0, 1, 1.f);
    dim3 gf2(DD/128, (BB*SS)/128, 1);
    gemm2<128,128,8,8,true,false,false><<<gf2,256>>>(ff, pw2, pb2, x2, nullptr, z,
        DFFF, DFFF, DFFF, DD, 1,0,1,0, 1,0,1,0, 1,0,1,0, 1, 1.f);
    run_ln(z, ln3_w, ln3_b, out, part, stats);
}

// round 8
// speedup vs baseline: 3.0645x; 2.0441x over previous
#include <cuda_runtime.h>
#include <cuda_bf16.h>
#include <cstdint>

// ---------------- problem constants ----------------
#define BB 8
#define SS 1024
#define DD 512
#define HH 8
#define DKK 64
#define DVV 64
#define DFFF 2048
#define SD (SS*DD)          // 524288 = 2^19
#define NEGV (-1e10f)

typedef __nv_bfloat16 bf16;

// ---------------- scratch (device globals; no allocation allowed) ----------------
__device__ bf16 g_xh[BB*SS*DD],  g_xl[BB*SS*DD];
__device__ bf16 g_yh[BB*SS*DD],  g_yl[BB*SS*DD];
__device__ bf16 g_qh[BB*SS*DD],  g_ql[BB*SS*DD];
__device__ bf16 g_kh[BB*SS*DD],  g_kl[BB*SS*DD];
__device__ float g_v[BB*SS*DD];
__device__ bf16 g_vth[BB*HH*DVV*SS], g_vtl[BB*HH*DVV*SS];
__device__ float g_sc[(size_t)BB*HH*SS*SS];                 // 256MB
__device__ bf16 g_ph[(size_t)BB*HH*SS*SS], g_pl[(size_t)BB*HH*SS*SS];
__device__ bf16 g_cath[BB*SS*DD], g_catl[BB*SS*DD];
__device__ float g_z [BB*SS*DD];
__device__ float g_x1[BB*SS*DD];
__device__ float g_x2[BB*SS*DD];
__device__ bf16 g_x1h[BB*SS*DD], g_x1l[BB*SS*DD];
__device__ bf16 g_x2h[BB*SS*DD], g_x2l[BB*SS*DD];
__device__ bf16 g_ffh[BB*SS*DFFF], g_ffl[BB*SS*DFFF];
__device__ bf16 g_wqh[DD*DD], g_wql[DD*DD];
__device__ bf16 g_wkh[DD*DD], g_wkl[DD*DD];
__device__ bf16 g_wvh[DD*DD], g_wvl[DD*DD];
__device__ bf16 g_woh[DD*DD], g_wol[DD*DD];
__device__ bf16 g_w1h[DFFF*DD], g_w1l[DFFF*DD];
__device__ bf16 g_w2h[DD*DFFF], g_w2l[DD*DFFF];
__device__ float2 g_part[BB*128];
__device__ float2 g_stats[BB];

// ---------------- helpers ----------------
__device__ __forceinline__ uint32_t smem_to_u32(const void* p) {
    uint32_t a;
    asm("{ .reg .u64 t; cvta.to.shared.u64 t, %1; cvt.u32.u64 %0, t; }" : "=r"(a) : "l"(p));
    return a;
}
__device__ __forceinline__ void ldsm4(uint32_t* r, uint32_t addr) {
    asm volatile("ldmatrix.sync.aligned.m8n8.x4.shared.b16 {%0,%1,%2,%3}, [%4];"
        : "=r"(r[0]), "=r"(r[1]), "=r"(r[2]), "=r"(r[3]) : "r"(addr));
}
__device__ __forceinline__ void mma16816(float* d, const uint32_t* a, uint32_t b0, uint32_t b1) {
    asm volatile("mma.sync.aligned.m16n8k16.row.col.f32.bf16.bf16.f32 "
        "{%0,%1,%2,%3}, {%4,%5,%6,%7}, {%8,%9}, {%0,%1,%2,%3};"
        : "+f"(d[0]), "+f"(d[1]), "+f"(d[2]), "+f"(d[3])
        : "r"(a[0]), "r"(a[1]), "r"(a[2]), "r"(a[3]), "r"(b0), "r"(b1));
}
__device__ __forceinline__ void split1(float v, bf16& h, bf16& l) {
    h = __float2bfloat16(v);
    l = __float2bfloat16(v - __bfloat162float(h));
}

// ================= bf16 split HMMA batched GEMM =================
// C = alpha * A * B^T (+bias)(+res)(mask)(relu). A[M,K], B[N,K] given as hi/lo bf16.
// M tile 128, N tile N_TILE, BK=32. 256 threads (8 warps).
template<int N_TILE, bool RELU, bool MASKED, bool WF32, bool WSPLIT>
__global__ void __launch_bounds__(256) gemm_mma(
    const bf16* __restrict__ Ah, const bf16* __restrict__ Al,
    const bf16* __restrict__ Bh, const bf16* __restrict__ Bl,
    const float* __restrict__ bias, const float* __restrict__ res,
    const int* __restrict__ maskp,
    float* __restrict__ C, bf16* __restrict__ Chi, bf16* __restrict__ Clo,
    int K, int lda, int ldb, int ldc,
    int divA, long long sA1, int modA, long long sA2,
    int divB, long long sB1, int modB, long long sB2,
    int divC, long long sC1, int modC, long long sC2,
    int maskDiv, float alpha)
{
    constexpr int WN = N_TILE / 32;          // warps along N
    constexpr int WM = 8 / WN;               // warps along M
    constexpr int MT = 128 / WM;             // warp M tile
    constexpr int MA = MT / 16;              // m16 atoms per warp
    constexpr int A_H = 0, A_L = 10240;
    constexpr int B_H = 20480;
    constexpr int BUFSZ = 20480 + 2 * N_TILE * 80;
    constexpr int A_PER = 2;                 // 512 uint4 / 256 threads
    constexpr int B_PER = (N_TILE * 4) / 256;

    extern __shared__ char smem[];
    const uint32_t sb = smem_to_u32(smem);

    const int tid  = threadIdx.x;
    const int lane = tid & 31;
    const int w    = tid >> 5;
    const int wm   = w / WN;
    const int wn   = w % WN;

    const int bz = blockIdx.z;
    const long long aoff = (long long)(bz / divA) * sA1 + (long long)(bz % modA) * sA2;
    const long long boff = (long long)(bz / divB) * sB1 + (long long)(bz % modB) * sB2;
    Ah += aoff; Al += aoff;
    Bh += boff; Bl += boff;
    const long long coff = (long long)(bz / divC) * sC1 + (long long)(bz % modC) * sC2;
    if (WF32) C += coff;
    if (WSPLIT) { Chi += coff; Clo += coff; }
    if (res) res += coff;
    const int* mrow = MASKED ? (maskp + (long long)(bz / maskDiv) * SS) : nullptr;

    const int row0 = blockIdx.y * 128;
    const int col0 = blockIdx.x * N_TILE;

    // ldmatrix per-lane address offsets (within a buffer)
    const int jj = lane >> 3, rr = lane & 7;
    const uint32_t aoffH = A_H + (uint32_t)(wm * MT + rr + (jj & 1) * 8) * 80 + (jj >> 1) * 16;
    const uint32_t boffH = B_H + (uint32_t)(wn * 32 + rr + (jj & 1) * 8) * 80 + (jj >> 1) * 16;

    float acc[MA][4][4] = {};
    uint4 pA[2][A_PER], pB[2][B_PER];

    auto load_tile = [&](int k0) {
        #pragma unroll
        for (int t = 0; t < A_PER; t++) {
            int idx = tid + t * 256;
            int r = idx >> 2, c = (idx & 3) * 8;
            long long o = (long long)(row0 + r) * lda + k0 + c;
            pA[0][t] = *(const uint4*)&Ah[o];
            pA[1][t] = *(const uint4*)&Al[o];
        }
        #pragma unroll
        for (int t = 0; t < B_PER; t++) {
            int idx = tid + t * 256;
            int r = idx >> 2, c = (idx & 3) * 8;
            long long o = (long long)(col0 + r) * ldb + k0 + c;
            pB[0][t] = *(const uint4*)&Bh[o];
            pB[1][t] = *(const uint4*)&Bl[o];
        }
    };
    auto store_tile = [&](int buf) {
        char* base = smem + buf * BUFSZ;
        #pragma unroll
        for (int t = 0; t < A_PER; t++) {
            int idx = tid + t * 256;
            int r = idx >> 2, cb = (idx & 3) * 16;
            *(uint4*)(base + A_H + r * 80 + cb) = pA[0][t];
            *(uint4*)(base + A_L + r * 80 + cb) = pA[1][t];
        }
        #pragma unroll
        for (int t = 0; t < B_PER; t++) {
            int idx = tid + t * 256;
            int r = idx >> 2, cb = (idx & 3) * 16;
            *(uint4*)(base + B_H + r * 80 + cb) = pB[0][t];
            *(uint4*)(base + B_H + N_TILE * 80 + r * 80 + cb) = pB[1][t];
        }
    };
    auto mma_tile = [&](int buf) {
        const uint32_t bbase = sb + buf * BUFSZ;
        #pragma unroll
        for (int ks = 0; ks < 2; ks++) {
            uint32_t ah[MA][4], al[MA][4];
            #pragma unroll
            for (int i = 0; i < MA; i++) {
                ldsm4(ah[i], bbase + aoffH + i * 1280 + ks * 32);
                ldsm4(al[i], bbase + aoffH + 10240 + i * 1280 + ks * 32);
            }
            #pragma unroll
            for (int p = 0; p < 2; p++) {
                uint32_t bh[4], bl[4];
                ldsm4(bh, bbase + boffH + p * 1280 + ks * 32);
                ldsm4(bl, bbase + boffH + N_TILE * 80 + p * 1280 + ks * 32);
                #pragma unroll
                for (int i = 0; i < MA; i++) {
                    mma16816(acc[i][2*p],   ah[i], bh[0], bh[2]);
                    mma16816(acc[i][2*p+1], ah[i], bh[1], bh[3]);
                    mma16816(acc[i][2*p],   ah[i], bl[0], bl[2]);
                    mma16816(acc[i][2*p+1], ah[i], bl[1], bl[3]);
                    mma16816(acc[i][2*p],   al[i], bh[0], bh[2]);
                    mma16816(acc[i][2*p+1], al[i], bh[1], bh[3]);
                }
            }
        }
    };

    const int NIT = K / 32;
    load_tile(0);
    store_tile(0);
    __syncthreads();
    for (int it = 0; it < NIT; it++) {
        const int buf = it & 1;
        const bool more = (it + 1 < NIT);
        if (more) load_tile((it + 1) * 32);
        mma_tile(buf);
        if (more) {
            store_tile(buf ^ 1);
            __syncthreads();
        }
    }

    // ---- epilogue ----
    #pragma unroll
    for (int i = 0; i < MA; i++) {
        const int rb = row0 + wm * MT + i * 16 + (lane >> 2);
        #pragma unroll
        for (int j = 0; j < 4; j++) {
            const int cn = col0 + wn * 32 + j * 8 + (lane & 3) * 2;
            #pragma unroll
            for (int half = 0; half < 2; half++) {
                const long long r = rb + half * 8;
                float v0 = acc[i][j][half * 2 + 0] * alpha;
                float v1 = acc[i][j][half * 2 + 1] * alpha;
                if (bias) {
                    float2 bv = *(const float2*)&bias[cn];
                    v0 += bv.x; v1 += bv.y;
                }
                if (res) {
                    float2 rv = *(const float2*)&res[r * ldc + cn];
                    v0 += rv.x; v1 += rv.y;
                }
                if (MASKED) {
                    int2 m = *(const int2*)&mrow[cn];
                    if (m.x == 0) v0 = NEGV;
                    if (m.y == 0) v1 = NEGV;
                }
                if (RELU) { v0 = fmaxf(v0, 0.f); v1 = fmaxf(v1, 0.f); }
                if (WF32) *(float2*)&C[r * ldc + cn] = make_float2(v0, v1);
                if (WSPLIT) {
                    bf16 h0, l0, h1, l1;
                    split1(v0, h0, l0);
                    split1(v1, h1, l1);
                    __nv_bfloat162 hp; hp.x = h0; hp.y = h1;
                    __nv_bfloat162 lp; lp.x = l0; lp.y = l1;
                    *(__nv_bfloat162*)&Chi[r * ldc + cn] = hp;
                    *(__nv_bfloat162*)&Clo[r * ldc + cn] = lp;
                }
            }
        }
    }
}

// ---------------- split fp32 -> bf16 hi/lo ----------------
__global__ void __launch_bounds__(256) split_f32(
    const float4* __restrict__ in, bf16* __restrict__ hi, bf16* __restrict__ lo, int n4)
{
    int idx = blockIdx.x * 256 + threadIdx.x;
    if (idx >= n4) return;
    float4 v = in[idx];
    bf16 h0,l0,h1,l1,h2,l2,h3,l3;
    split1(v.x,h0,l0); split1(v.y,h1,l1); split1(v.z,h2,l2); split1(v.w,h3,l3);
    __nv_bfloat162* hp = (__nv_bfloat162*)(hi + (size_t)idx*4);
    __nv_bfloat162* lp = (__nv_bfloat162*)(lo + (size_t)idx*4);
    __nv_bfloat162 a; a.x=h0; a.y=h1; __nv_bfloat162 b; b.x=h2; b.y=h3;
    hp[0]=a; hp[1]=b;
    a.x=l0; a.y=l1; b.x=l2; b.y=l3;
    lp[0]=a; lp[1]=b;
}

// ---------------- weight repack+split: [H,D,DK] -> [N=H*DK, K=D] hi/lo ----------------
__global__ void __launch_bounds__(256) repack_w(
    const float* __restrict__ w, bf16* __restrict__ oh, bf16* __restrict__ ol)
{
    int idx = blockIdx.x * 256 + threadIdx.x;   // over H*D*DK = 2^18
    int j = idx & 63;             // dk
    int d = (idx >> 6) & 511;     // d
    int h = idx >> 15;            // h
    bf16 hi, lo;
    split1(w[idx], hi, lo);
    int o = (h * DKK + j) * DD + d;
    oh[o] = hi; ol[o] = lo;
}

// ---------------- v transpose+split: [B,S,H*64] f32 -> [B,H,64,S] hi/lo ----------------
__global__ void __launch_bounds__(256) transpose_v(
    const float* __restrict__ v, bf16* __restrict__ vth, bf16* __restrict__ vtl)
{
    __shared__ float tile[32][33];
    const int bh = blockIdx.z;
    const int b = bh >> 3, h = bh & 7;
    const int s0 = blockIdx.x * 32, d0 = blockIdx.y * 32;
    const int ty0 = threadIdx.y;            // 0..7
    #pragma unroll
    for (int rs = 0; rs < 4; rs++) {
        int ty = ty0 + rs * 8;
        tile[ty][threadIdx.x] =
            v[((long long)b * SS + s0 + ty) * DD + h * 64 + d0 + threadIdx.x];
    }
    __syncthreads();
    #pragma unroll
    for (int rs = 0; rs < 4; rs++) {
        int ty = ty0 + rs * 8;
        float val = tile[threadIdx.x][ty];
        bf16 hi, lo;
        split1(val, hi, lo);
        long long o = ((long long)bh * 64 + d0 + ty) * SS + s0 + threadIdx.x;
        vth[o] = hi; vtl[o] = lo;
    }
}

// ---------------- softmax over key dim -> split probs ----------------
__global__ void __launch_bounds__(256) softmax_kernel(
    const float* __restrict__ sc, bf16* __restrict__ ph, bf16* __restrict__ pl)
{
    const long long row = blockIdx.x;
    const float4* p = (const float4*)sc + row * 256;
    const int t = threadIdx.x;
    float4 v = p[t];

    __shared__ float smx[8];
    __shared__ float ssm[8];
    const int lane = t & 31, w = t >> 5;

    float mx = fmaxf(fmaxf(v.x, v.y), fmaxf(v.z, v.w));
    #pragma unroll
    for (int o = 16; o; o >>= 1) mx = fmaxf(mx, __shfl_xor_sync(0xffffffffu, mx, o));
    if (lane == 0) smx[w] = mx;
    __syncthreads();
    float bm = smx[0];
    #pragma unroll
    for (int j = 1; j < 8; j++) bm = fmaxf(bm, smx[j]);

    float4 e;
    e.x = __expf(v.x - bm);
    e.y = __expf(v.y - bm);
    e.z = __expf(v.z - bm);
    e.w = __expf(v.w - bm);
    float s = e.x + e.y + e.z + e.w;
    #pragma unroll
    for (int o = 16; o; o >>= 1) s += __shfl_xor_sync(0xffffffffu, s, o);
    if (lane == 0) ssm[w] = s;
    __syncthreads();
    float tot = 0.f;
    #pragma unroll
    for (int j = 0; j < 8; j++) tot += ssm[j];
    float inv = 1.f / tot;
    e.x *= inv; e.y *= inv; e.z *= inv; e.w *= inv;

    bf16 h0,l0,h1,l1,h2,l2,h3,l3;
    split1(e.x,h0,l0); split1(e.y,h1,l1); split1(e.z,h2,l2); split1(e.w,h3,l3);
    __nv_bfloat162* hp = (__nv_bfloat162*)(ph + row * SS + t * 4);
    __nv_bfloat162* lp = (__nv_bfloat162*)(pl + row * SS + t * 4);
    __nv_bfloat162 a; a.x=h0; a.y=h1; __nv_bfloat162 b; b.x=h2; b.y=h3;
    hp[0]=a; hp[1]=b;
    a.x=l0; a.y=l1; b.x=l2; b.y=l3;
    lp[0]=a; lp[1]=b;
}

// ---------------- LayerNorm over whole [S,D] per batch ----------------
__global__ void __launch_bounds__(256) ln_partial_kernel(
    const float* __restrict__ z, float2* __restrict__ part)
{
    const long long base = (long long)blockIdx.x * 4096;
    const float4* p = (const float4*)(z + base);
    float s = 0.f, q = 0.f;
    for (int i = threadIdx.x; i < 1024; i += 256) {
        float4 v = p[i];
        s += v.x + v.y + v.z + v.w;
        q += v.x*v.x + v.y*v.y + v.z*v.z + v.w*v.w;
    }
    __shared__ float ss[8], sq[8];
    const int lane = threadIdx.x & 31, w = threadIdx.x >> 5;
    #pragma unroll
    for (int o = 16; o; o >>= 1) {
        s += __shfl_xor_sync(0xffffffffu, s, o);
        q += __shfl_xor_sync(0xffffffffu, q, o);
    }
    if (lane == 0) { ss[w] = s; sq[w] = q; }
    __syncthreads();
    if (threadIdx.x == 0) {
        float ts = 0.f, tq = 0.f;
        #pragma unroll
        for (int j = 0; j < 8; j++) { ts += ss[j]; tq += sq[j]; }
        part[blockIdx.x] = make_float2(ts, tq);
    }
}

__global__ void __launch_bounds__(128) ln_final_kernel(
    const float2* __restrict__ part, float2* __restrict__ stats)
{
    float2 v = part[blockIdx.x * 128 + threadIdx.x];
    float s = v.x, q = v.y;
    __shared__ float ss[4], sq[4];
    const int lane = threadIdx.x & 31, w = threadIdx.x >> 5;
    #pragma unroll
    for (int o = 16; o; o >>= 1) {
        s += __shfl_xor_sync(0xffffffffu, s, o);
        q += __shfl_xor_sync(0xffffffffu, q, o);
    }
    if (lane == 0) { ss[w] = s; sq[w] = q; }
    __syncthreads();
    if (threadIdx.x == 0) {
        float ts = 0.f, tq = 0.f;
        #pragma unroll
        for (int j = 0; j < 4; j++) { ts += ss[j]; tq += sq[j]; }
        float mean = ts * (1.f / SD);
        float var = tq * (1.f / SD) - mean * mean;
        stats[blockIdx.x] = make_float2(mean, rsqrtf(var + 1e-6f));
    }
}

template<bool SPLIT>
__global__ void __launch_bounds__(256) ln_apply_kernel(
    const float* __restrict__ z, const float2* __restrict__ stats,
    const float* __restrict__ w, const float* __restrict__ bias,
    float* __restrict__ out, bf16* __restrict__ oh, bf16* __restrict__ ol)
{
    const int idx = blockIdx.x * 256 + threadIdx.x;
    const long long linear = (long long)idx * 4;
    const int b = (int)(linear >> 19);
    const int sd = (int)(linear & (SD - 1));
    float2 st = stats[b];
    float4 v  = ((const float4*)z)[idx];
    float4 wv = ((const float4*)w)[sd >> 2];
    float4 bv = ((const float4*)bias)[sd >> 2];
    float4 o;
    o.x = (v.x - st.x) * st.y * wv.x + bv.x;
    o.y = (v.y - st.x) * st.y * wv.y + bv.y;
    o.z = (v.z - st.x) * st.y * wv.z + bv.z;
    o.w = (v.w - st.x) * st.y * wv.w + bv.w;
    ((float4*)out)[idx] = o;
    if (SPLIT) {
        bf16 h0,l0,h1,l1,h2,l2,h3,l3;
        split1(o.x,h0,l0); split1(o.y,h1,l1); split1(o.z,h2,l2); split1(o.w,h3,l3);
        __nv_bfloat162* hp = (__nv_bfloat162*)(oh + (size_t)idx*4);
        __nv_bfloat162* lp = (__nv_bfloat162*)(ol + (size_t)idx*4);
        __nv_bfloat162 a; a.x=h0; a.y=h1; __nv_bfloat162 c; c.x=h2; c.y=h3;
        hp[0]=a; hp[1]=c;
        a.x=l0; a.y=l1; c.x=l2; c.y=l3;
        lp[0]=a; lp[1]=c;
    }
}

// ---------------- host orchestration ----------------
#define SM128 (2*(20480 + 2*128*80))   // 81920
#define SM64  (2*(20480 + 2*64*80))    // 61440

struct Ptrs {
    bf16 *xh,*xl,*yh,*yl,*qh,*ql,*kh,*kl,*vth,*vtl,*ph,*pl,*cath,*catl;
    bf16 *x1h,*x1l,*x2h,*x2l,*ffh,*ffl;
    bf16 *wqh,*wql,*wkh,*wkl,*wvh,*wvl,*woh,*wol,*w1h,*w1l,*w2h,*w2l;
    float *v,*sc,*z,*x1,*x2;
    float2 *part,*stats;
};

static void run_ln(const float* z, const float* w, const float* b, float* out,
                   bf16* oh, bf16* ol, Ptrs& P)
{
    ln_partial_kernel<<<BB*128, 256>>>(z, P.part);
    ln_final_kernel<<<BB, 128>>>(P.part, P.stats);
    if (oh) ln_apply_kernel<true ><<<(BB*SD)/(256*4), 256>>>(z, P.stats, w, b, out, oh, ol);
    else    ln_apply_kernel<false><<<(BB*SD)/(256*4), 256>>>(z, P.stats, w, b, out, nullptr, nullptr);
}

static void run_mha(const bf16* qinh, const bf16* qinl,
                    const bf16* kinh, const bf16* kinl,
                    const float* wq, const float* bq,
                    const float* wk, const float* bk,
                    const float* wv, const float* bv,
                    const float* wo, const float* bo,
                    const int* mask, const float* resid,
                    Ptrs& P, float* zout)
{
    repack_w<<<1024, 256>>>(wq, P.wqh, P.wql);
    repack_w<<<1024, 256>>>(wk, P.wkh, P.wkl);
    repack_w<<<1024, 256>>>(wv, P.wvh, P.wvl);
    split_f32<<<(DD*DD/4+255)/256, 256>>>((const float4*)wo, P.woh, P.wol, DD*DD/4);

    // projections: [B*S,512] x [512,512]^T
    dim3 gp(DD/128, (BB*SS)/128, 1);
    gemm_mma<128,false,false,false,true><<<gp,256,SM128>>>(
        qinh, qinl, P.wqh, P.wql, bq, nullptr, nullptr,
        nullptr, P.qh, P.ql,
        DD, DD, DD, DD, 1,0,1,0, 1,0,1,0, 1,0,1,0, 1, 1.f);
    gemm_mma<128,false,false,false,true><<<gp,256,SM128>>>(
        kinh, kinl, P.wkh, P.wkl, bk, nullptr, nullptr,
        nullptr, P.kh, P.kl,
        DD, DD, DD, DD, 1,0,1,0, 1,0,1,0, 1,0,1,0, 1, 1.f);
    gemm_mma<128,false,false,true,false><<<gp,256,SM128>>>(
        kinh, kinl, P.wvh, P.wvl, bv, nullptr, nullptr,
        P.v, nullptr, nullptr,
        DD, DD, DD, DD, 1,0,1,0, 1,0,1,0, 1,0,1,0, 1, 1.f);

    transpose_v<<<dim3(SS/32, 2, BB*HH), dim3(32,8)>>>(P.v, P.vth, P.vtl);

    // scores = (q @ k^T)/8 + mask
    dim3 gs(SS/128, SS/128, BB*HH);
    gemm_mma<128,false,true,true,false><<<gs,256,SM128>>>(
        P.qh, P.ql, P.kh, P.kl, nullptr, nullptr, mask,
        P.sc, nullptr, nullptr,
        DKK, DD, DD, SS,
        HH, (long long)SS*DD, HH, DKK,
        HH, (long long)SS*DD, HH, DKK,
        1, (long long)SS*SS, 1, 0,
        HH, 0.125f);

    softmax_kernel<<<BB*HH*SS, 256>>>(P.sc, P.ph, P.pl);

    // AV: probs [S,S] x vt[64,S]^T -> cat split [B,S,H*64]
    dim3 ga(1, SS/128, BB*HH);
    gemm_mma<64,false,false,false,true><<<ga,256,SM64>>>(
        P.ph, P.pl, P.vth, P.vtl, nullptr, nullptr, nullptr,
        nullptr, P.cath, P.catl,
        SS, SS, SS, DD,
        1, (long long)SS*SS, 1, 0,
        1, (long long)DVV*SS, 1, 0,
        HH, (long long)SS*DD, HH, (long long)DVV,
        1, 1.f);

    // out projection + bias + residual
    dim3 go(DD/128, (BB*SS)/128, 1);
    gemm_mma<128,false,false,true,false><<<go,256,SM128>>>(
        P.cath, P.catl, P.woh, P.wol, bo, resid, nullptr,
        zout, nullptr, nullptr,
        DD, DD, DD, DD, 1,0,1,0, 1,0,1,0, 1,0,1,0, 1, 1.f);
}

extern "C" void kernel_launch(void* const* d_in, const int* in_sizes, int n_in,
                              void* d_out, int out_size)
{
    const float* x        = (const float*)d_in[0];
    const float* y        = (const float*)d_in[1];
    const int*   src_mask = (const int*)  d_in[2];
    const int*   trg_mask = (const int*)  d_in[3];
    const float* m1_wq = (const float*)d_in[4];
    const float* m1_bq = (const float*)d_in[5];
    const float* m1_wk = (const float*)d_in[6];
    const float* m1_bk = (const float*)d_in[7];
    const float* m1_wv = (const float*)d_in[8];
    const float* m1_bv = (const float*)d_in[9];
    const float* m1_wo = (const float*)d_in[10];
    const float* m1_bo = (const float*)d_in[11];
    const float* m2_wq = (const float*)d_in[12];
    const float* m2_bq = (const float*)d_in[13];
    const float* m2_wk = (const float*)d_in[14];
    const float* m2_bk = (const float*)d_in[15];
    const float* m2_wv = (const float*)d_in[16];
    const float* m2_bv = (const float*)d_in[17];
    const float* m2_wo = (const float*)d_in[18];
    const float* m2_bo = (const float*)d_in[19];
    const float* pw1   = (const float*)d_in[20];
    const float* pb1   = (const float*)d_in[21];
    const float* pw2   = (const float*)d_in[22];
    const float* pb2   = (const float*)d_in[23];
    const float* ln1_w = (const float*)d_in[24];
    const float* ln1_b = (const float*)d_in[25];
    const float* ln2_w = (const float*)d_in[26];
    const float* ln2_b = (const float*)d_in[27];
    const float* ln3_w = (const float*)d_in[28];
    const float* ln3_b = (const float*)d_in[29];
    float* out = (float*)d_out;

    Ptrs P;
    cudaGetSymbolAddress((void**)&P.xh, g_xh);   cudaGetSymbolAddress((void**)&P.xl, g_xl);
    cudaGetSymbolAddress((void**)&P.yh, g_yh);   cudaGetSymbolAddress((void**)&P.yl, g_yl);
    cudaGetSymbolAddress((void**)&P.qh, g_qh);   cudaGetSymbolAddress((void**)&P.ql, g_ql);
    cudaGetSymbolAddress((void**)&P.kh, g_kh);   cudaGetSymbolAddress((void**)&P.kl, g_kl);
    cudaGetSymbolAddress((void**)&P.vth, g_vth); cudaGetSymbolAddress((void**)&P.vtl, g_vtl);
    cudaGetSymbolAddress((void**)&P.ph, g_ph);   cudaGetSymbolAddress((void**)&P.pl, g_pl);
    cudaGetSymbolAddress((void**)&P.cath, g_cath); cudaGetSymbolAddress((void**)&P.catl, g_catl);
    cudaGetSymbolAddress((void**)&P.x1h, g_x1h); cudaGetSymbolAddress((void**)&P.x1l, g_x1l);
    cudaGetSymbolAddress((void**)&P.x2h, g_x2h); cudaGetSymbolAddress((void**)&P.x2l, g_x2l);
    cudaGetSymbolAddress((void**)&P.ffh, g_ffh); cudaGetSymbolAddress((void**)&P.ffl, g_ffl);
    cudaGetSymbolAddress((void**)&P.wqh, g_wqh); cudaGetSymbolAddress((void**)&P.wql, g_wql);
    cudaGetSymbolAddress((void**)&P.wkh, g_wkh); cudaGetSymbolAddress((void**)&P.wkl, g_wkl);
    cudaGetSymbolAddress((void**)&P.wvh, g_wvh); cudaGetSymbolAddress((void**)&P.wvl, g_wvl);
    cudaGetSymbolAddress((void**)&P.woh, g_woh); cudaGetSymbolAddress((void**)&P.wol, g_wol);
    cudaGetSymbolAddress((void**)&P.w1h, g_w1h); cudaGetSymbolAddress((void**)&P.w1l, g_w1l);
    cudaGetSymbolAddress((void**)&P.w2h, g_w2h); cudaGetSymbolAddress((void**)&P.w2l, g_w2l);
    cudaGetSymbolAddress((void**)&P.v, g_v);
    cudaGetSymbolAddress((void**)&P.sc, g_sc);
    cudaGetSymbolAddress((void**)&P.z, g_z);
    cudaGetSymbolAddress((void**)&P.x1, g_x1);
    cudaGetSymbolAddress((void**)&P.x2, g_x2);
    cudaGetSymbolAddress((void**)&P.part, g_part);
    cudaGetSymbolAddress((void**)&P.stats, g_stats);

    cudaFuncSetAttribute(gemm_mma<128,false,false,false,true>, cudaFuncAttributeMaxDynamicSharedMemorySize, SM128);
    cudaFuncSetAttribute(gemm_mma<128,false,false,true,false>, cudaFuncAttributeMaxDynamicSharedMemorySize, SM128);
    cudaFuncSetAttribute(gemm_mma<128,false,true ,true,false>, cudaFuncAttributeMaxDynamicSharedMemorySize, SM128);
    cudaFuncSetAttribute(gemm_mma<128,true ,false,false,true>, cudaFuncAttributeMaxDynamicSharedMemorySize, SM128);
    cudaFuncSetAttribute(gemm_mma<64 ,false,false,false,true>, cudaFuncAttributeMaxDynamicSharedMemorySize, SM64);

    // split inputs once
    split_f32<<<(BB*SD/4+255)/256, 256>>>((const float4*)x, P.xh, P.xl, BB*SD/4);
    split_f32<<<(BB*SD/4+255)/256, 256>>>((const float4*)y, P.yh, P.yl, BB*SD/4);
    split_f32<<<(DFFF*DD/4+255)/256, 256>>>((const float4*)pw1, P.w1h, P.w1l, DFFF*DD/4);
    split_f32<<<(DD*DFFF/4+255)/256, 256>>>((const float4*)pw2, P.w2h, P.w2l, DD*DFFF/4);

    // 1) self-attention (trg_mask) + residual, LN1 -> x1 (+split)
    run_mha(P.xh, P.xl, P.xh, P.xl,
            m1_wq, m1_bq, m1_wk, m1_bk, m1_wv, m1_bv, m1_wo, m1_bo,
            trg_mask, x, P, P.z);
    run_ln(P.z, ln1_w, ln1_b, P.x1, P.x1h, P.x1l, P);

    // 2) cross-attention (q from x1, k/v from y; src_mask) + residual, LN2 -> x2 (+split)
    run_mha(P.x1h, P.x1l, P.yh, P.yl,
            m2_wq, m2_bq, m2_wk, m2_bk, m2_wv, m2_bv, m2_wo, m2_bo,
            src_mask, P.x1, P, P.z);
    run_ln(P.z, ln2_w, ln2_b, P.x2, P.x2h, P.x2l, P);

    // 3) FFN + residual, LN3 -> out
    dim3 gf1(DFFF/128, (BB*SS)/128, 1);
    gemm_mma<128,true,false,false,true><<<gf1,256,SM128>>>(
        P.x2h, P.x2l, P.w1h, P.w1l, pb1, nullptr, nullptr,
        nullptr, P.ffh, P.ffl,
        DD, DD, DD, DFFF, 1,0,1,0, 1,0,1,0, 1,0,1,0, 1, 1.f);
    dim3 gf2(DD/128, (BB*SS)/128, 1);
    gemm_mma<128,false,false,true,false><<<gf2,256,SM128>>>(
        P.ffh, P.ffl, P.w2h, P.w2l, pb2, P.x2, nullptr,
        P.z, nullptr, nullptr,
        DFFF, DFFF, DFFF, DD, 1,0,1,0, 1,0,1,0, 1,0,1,0, 1, 1.f);
    run_ln(P.z, ln3_w, ln3_b, out, nullptr, nullptr, P);
}

// round 9
// speedup vs baseline: 3.8509x; 1.2566x over previous
#include <cuda_runtime.h>
#include <cuda_bf16.h>
#include <cstdint>

// ---------------- problem constants ----------------
#define BB 8
#define SS 1024
#define DD 512
#define HH 8
#define DKK 64
#define DVV 64
#define DFFF 2048
#define SD (SS*DD)          // 524288 = 2^19
#define NEGV (-1e10f)

typedef __nv_bfloat16 bf16;

// ---------------- scratch (device globals; no allocation allowed) ----------------
__device__ bf16 g_xh[BB*SS*DD],  g_xl[BB*SS*DD];
__device__ bf16 g_yh[BB*SS*DD],  g_yl[BB*SS*DD];
__device__ bf16 g_qh[BB*SS*DD],  g_ql[BB*SS*DD];
__device__ bf16 g_kh[BB*SS*DD],  g_kl[BB*SS*DD];
__device__ float g_v[BB*SS*DD];
__device__ bf16 g_vth[BB*HH*DVV*SS], g_vtl[BB*HH*DVV*SS];
__device__ bf16 g_cath[BB*SS*DD], g_catl[BB*SS*DD];
__device__ float g_z [BB*SS*DD];
__device__ float g_x1[BB*SS*DD];
__device__ float g_x2[BB*SS*DD];
__device__ bf16 g_x1h[BB*SS*DD], g_x1l[BB*SS*DD];
__device__ bf16 g_x2h[BB*SS*DD], g_x2l[BB*SS*DD];
__device__ bf16 g_ffh[BB*SS*DFFF], g_ffl[BB*SS*DFFF];
__device__ bf16 g_wqh[DD*DD], g_wql[DD*DD];
__device__ bf16 g_wkh[DD*DD], g_wkl[DD*DD];
__device__ bf16 g_wvh[DD*DD], g_wvl[DD*DD];
__device__ bf16 g_woh[DD*DD], g_wol[DD*DD];
__device__ bf16 g_w1h[DFFF*DD], g_w1l[DFFF*DD];
__device__ bf16 g_w2h[DD*DFFF], g_w2l[DD*DFFF];
__device__ float2 g_part[BB*128];
__device__ float2 g_stats[BB];

// ---------------- helpers ----------------
__device__ __forceinline__ uint32_t smem_to_u32(const void* p) {
    uint32_t a;
    asm("{ .reg .u64 t; cvta.to.shared.u64 t, %1; cvt.u32.u64 %0, t; }" : "=r"(a) : "l"(p));
    return a;
}
__device__ __forceinline__ void ldsm4(uint32_t* r, uint32_t addr) {
    asm volatile("ldmatrix.sync.aligned.m8n8.x4.shared.b16 {%0,%1,%2,%3}, [%4];"
        : "=r"(r[0]), "=r"(r[1]), "=r"(r[2]), "=r"(r[3]) : "r"(addr));
}
__device__ __forceinline__ void mma16816(float* d, const uint32_t* a, uint32_t b0, uint32_t b1) {
    asm volatile("mma.sync.aligned.m16n8k16.row.col.f32.bf16.bf16.f32 "
        "{%0,%1,%2,%3}, {%4,%5,%6,%7}, {%8,%9}, {%0,%1,%2,%3};"
        : "+f"(d[0]), "+f"(d[1]), "+f"(d[2]), "+f"(d[3])
        : "r"(a[0]), "r"(a[1]), "r"(a[2]), "r"(a[3]), "r"(b0), "r"(b1));
}
__device__ __forceinline__ void split1(float v, bf16& h, bf16& l) {
    h = __float2bfloat16(v);
    l = __float2bfloat16(v - __bfloat162float(h));
}
__device__ __forceinline__ uint32_t packbf2(float a, float b) {
    __nv_bfloat162 t = __floats2bfloat162_rn(a, b);
    return *reinterpret_cast<uint32_t*>(&t);
}

// ================= bf16 split HMMA batched GEMM =================
// C = alpha * A * B^T (+bias)(+res)(relu). A[M,K], B[N,K] given as hi/lo bf16.
// M tile 128, N tile N_TILE, BK=32. 256 threads (8 warps).
template<int N_TILE, bool RELU, bool WF32, bool WSPLIT>
__global__ void __launch_bounds__(256) gemm_mma(
    const bf16* __restrict__ Ah, const bf16* __restrict__ Al,
    const bf16* __restrict__ Bh, const bf16* __restrict__ Bl,
    const float* __restrict__ bias, const float* __restrict__ res,
    float* __restrict__ C, bf16* __restrict__ Chi, bf16* __restrict__ Clo,
    int K, int lda, int ldb, int ldc,
    int divA, long long sA1, int modA, long long sA2,
    int divB, long long sB1, int modB, long long sB2,
    int divC, long long sC1, int modC, long long sC2,
    float alpha)
{
    constexpr int WN = N_TILE / 32;          // warps along N
    constexpr int WM = 8 / WN;               // warps along M
    constexpr int MT = 128 / WM;             // warp M tile
    constexpr int MA = MT / 16;              // m16 atoms per warp
    constexpr int A_H = 0, A_L = 10240;
    constexpr int B_H = 20480;
    constexpr int BUFSZ = 20480 + 2 * N_TILE * 80;
    constexpr int A_PER = 2;                 // 512 uint4 / 256 threads
    constexpr int B_PER = (N_TILE * 4) / 256;

    extern __shared__ char smem[];
    const uint32_t sb = smem_to_u32(smem);

    const int tid  = threadIdx.x;
    const int lane = tid & 31;
    const int w    = tid >> 5;
    const int wm   = w / WN;
    const int wn   = w % WN;

    const int bz = blockIdx.z;
    const long long aoff = (long long)(bz / divA) * sA1 + (long long)(bz % modA) * sA2;
    const long long boff = (long long)(bz / divB) * sB1 + (long long)(bz % modB) * sB2;
    Ah += aoff; Al += aoff;
    Bh += boff; Bl += boff;
    const long long coff = (long long)(bz / divC) * sC1 + (long long)(bz % modC) * sC2;
    if (WF32) C += coff;
    if (WSPLIT) { Chi += coff; Clo += coff; }
    if (res) res += coff;

    const int row0 = blockIdx.y * 128;
    const int col0 = blockIdx.x * N_TILE;

    const int jj = lane >> 3, rr = lane & 7;
    const uint32_t aoffH = A_H + (uint32_t)(wm * MT + rr + (jj & 1) * 8) * 80 + (jj >> 1) * 16;
    const uint32_t boffH = B_H + (uint32_t)(wn * 32 + rr + (jj & 1) * 8) * 80 + (jj >> 1) * 16;

    float acc[MA][4][4] = {};
    uint4 pA[2][A_PER], pB[2][B_PER];

    auto load_tile = [&](int k0) {
        #pragma unroll
        for (int t = 0; t < A_PER; t++) {
            int idx = tid + t * 256;
            int r = idx >> 2, c = (idx & 3) * 8;
            long long o = (long long)(row0 + r) * lda + k0 + c;
            pA[0][t] = *(const uint4*)&Ah[o];
            pA[1][t] = *(const uint4*)&Al[o];
        }
        #pragma unroll
        for (int t = 0; t < B_PER; t++) {
            int idx = tid + t * 256;
            int r = idx >> 2, c = (idx & 3) * 8;
            long long o = (long long)(col0 + r) * ldb + k0 + c;
            pB[0][t] = *(const uint4*)&Bh[o];
            pB[1][t] = *(const uint4*)&Bl[o];
        }
    };
    auto store_tile = [&](int buf) {
        char* base = smem + buf * BUFSZ;
        #pragma unroll
        for (int t = 0; t < A_PER; t++) {
            int idx = tid + t * 256;
            int r = idx >> 2, cb = (idx & 3) * 16;
            *(uint4*)(base + A_H + r * 80 + cb) = pA[0][t];
            *(uint4*)(base + A_L + r * 80 + cb) = pA[1][t];
        }
        #pragma unroll
        for (int t = 0; t < B_PER; t++) {
            int idx = tid + t * 256;
            int r = idx >> 2, cb = (idx & 3) * 16;
            *(uint4*)(base + B_H + r * 80 + cb) = pB[0][t];
            *(uint4*)(base + B_H + N_TILE * 80 + r * 80 + cb) = pB[1][t];
        }
    };
    auto mma_tile = [&](int buf) {
        const uint32_t bbase = sb + buf * BUFSZ;
        #pragma unroll
        for (int ks = 0; ks < 2; ks++) {
            uint32_t ah[MA][4], al[MA][4];
            #pragma unroll
            for (int i = 0; i < MA; i++) {
                ldsm4(ah[i], bbase + aoffH + i * 1280 + ks * 32);
                ldsm4(al[i], bbase + aoffH + 10240 + i * 1280 + ks * 32);
            }
            #pragma unroll
            for (int p = 0; p < 2; p++) {
                uint32_t bh[4], bl[4];
                ldsm4(bh, bbase + boffH + p * 1280 + ks * 32);
                ldsm4(bl, bbase + boffH + N_TILE * 80 + p * 1280 + ks * 32);
                #pragma unroll
                for (int i = 0; i < MA; i++) {
                    mma16816(acc[i][2*p],   ah[i], bh[0], bh[2]);
                    mma16816(acc[i][2*p+1], ah[i], bh[1], bh[3]);
                    mma16816(acc[i][2*p],   ah[i], bl[0], bl[2]);
                    mma16816(acc[i][2*p+1], ah[i], bl[1], bl[3]);
                    mma16816(acc[i][2*p],   al[i], bh[0], bh[2]);
                    mma16816(acc[i][2*p+1], al[i], bh[1], bh[3]);
                }
            }
        }
    };

    const int NIT = K / 32;
    load_tile(0);
    store_tile(0);
    __syncthreads();
    for (int it = 0; it < NIT; it++) {
        const int buf = it & 1;
        const bool more = (it + 1 < NIT);
        if (more) load_tile((it + 1) * 32);
        mma_tile(buf);
        if (more) {
            store_tile(buf ^ 1);
            __syncthreads();
        }
    }

    // ---- epilogue ----
    #pragma unroll
    for (int i = 0; i < MA; i++) {
        const int rb = row0 + wm * MT + i * 16 + (lane >> 2);
        #pragma unroll
        for (int j = 0; j < 4; j++) {
            const int cn = col0 + wn * 32 + j * 8 + (lane & 3) * 2;
            #pragma unroll
            for (int half = 0; half < 2; half++) {
                const long long r = rb + half * 8;
                float v0 = acc[i][j][half * 2 + 0] * alpha;
                float v1 = acc[i][j][half * 2 + 1] * alpha;
                if (bias) {
                    float2 bv = *(const float2*)&bias[cn];
                    v0 += bv.x; v1 += bv.y;
                }
                if (res) {
                    float2 rv = *(const float2*)&res[r * ldc + cn];
                    v0 += rv.x; v1 += rv.y;
                }
                if (RELU) { v0 = fmaxf(v0, 0.f); v1 = fmaxf(v1, 0.f); }
                if (WF32) *(float2*)&C[r * ldc + cn] = make_float2(v0, v1);
                if (WSPLIT) {
                    bf16 h0, l0, h1, l1;
                    split1(v0, h0, l0);
                    split1(v1, h1, l1);
                    __nv_bfloat162 hp; hp.x = h0; hp.y = h1;
                    __nv_bfloat162 lp; lp.x = l0; lp.y = l1;
                    *(__nv_bfloat162*)&Chi[r * ldc + cn] = hp;
                    *(__nv_bfloat162*)&Clo[r * ldc + cn] = lp;
                }
            }
        }
    }
}

// ================= fused flash attention =================
// grid (8 q-tiles, B*H). 256 threads = 8 warps x 16 rows. 3-pass split HMMA both GEMMs.
#define FLQ_H 0
#define FLQ_L 18432
#define FLK_H 36864
#define FLK_L 55296
#define FLV_H 73728
#define FLV_L 91136
#define FLMASK 108544
#define FL_SMEM 109056

__global__ void __launch_bounds__(256) flash_attn(
    const bf16* __restrict__ qhp, const bf16* __restrict__ qlp,
    const bf16* __restrict__ khp, const bf16* __restrict__ klp,
    const bf16* __restrict__ vthp, const bf16* __restrict__ vtlp,
    const int* __restrict__ maskp,
    bf16* __restrict__ cath, bf16* __restrict__ catl)
{
    extern __shared__ char smem[];
    const uint32_t sb = smem_to_u32(smem);
    const int tid = threadIdx.x;
    const int lane = tid & 31;
    const int w = tid >> 5;
    const int bh = blockIdx.y;
    const int b = bh >> 3, h = bh & 7;
    const int q0 = blockIdx.x * 128;

    // ---- load Q tile (hi/lo), 128x64, smem row stride 144B ----
    const long long qgbase = ((long long)b * SS + q0) * DD + h * 64;
    #pragma unroll
    for (int t = 0; t < 4; t++) {
        int idx = tid + t * 256;
        int r = idx >> 3, c = (idx & 7) * 8;
        long long o = qgbase + (long long)r * DD + c;
        *(uint4*)(smem + FLQ_H + r * 144 + c * 2) = *(const uint4*)&qhp[o];
        *(uint4*)(smem + FLQ_L + r * 144 + c * 2) = *(const uint4*)&qlp[o];
    }
    __syncthreads();

    const int jj = lane >> 3, rr = lane & 7;
    const uint32_t aoffQ = sb + FLQ_H + (uint32_t)(w * 16 + rr + (jj & 1) * 8) * 144 + (jj >> 1) * 16;
    uint32_t qa[4][4], qla[4][4];
    #pragma unroll
    for (int ks = 0; ks < 4; ks++) {
        ldsm4(qa[ks],  aoffQ + ks * 32);
        ldsm4(qla[ks], aoffQ + 18432 + ks * 32);
    }
    const uint32_t boffK = sb + FLK_H + (uint32_t)(rr + (jj & 1) * 8) * 144 + (jj >> 1) * 16;
    const uint32_t boffV = sb + FLV_H + (uint32_t)(rr + (jj & 1) * 8) * 272 + (jj >> 1) * 16;

    float oacc[8][4] = {};
    float mold0 = -3e38f, mold1 = -3e38f;
    float lsum0 = 0.f, lsum1 = 0.f;

    for (int kt = 0; kt < 8; kt++) {
        __syncthreads();    // previous iteration's ldsm complete before overwrite
        // K tile 128x64 (hi/lo)
        const long long kgbase = ((long long)b * SS + kt * 128) * DD + h * 64;
        #pragma unroll
        for (int t = 0; t < 4; t++) {
            int idx = tid + t * 256;
            int r = idx >> 3, c = (idx & 7) * 8;
            long long o = kgbase + (long long)r * DD + c;
            *(uint4*)(smem + FLK_H + r * 144 + c * 2) = *(const uint4*)&khp[o];
            *(uint4*)(smem + FLK_L + r * 144 + c * 2) = *(const uint4*)&klp[o];
        }
        // VT tile 64x128 (hi/lo), row stride 272B
        const long long vgbase = ((long long)bh * 64) * SS + kt * 128;
        #pragma unroll
        for (int t = 0; t < 4; t++) {
            int idx = tid + t * 256;
            int r = idx >> 4, c = (idx & 15) * 8;
            long long o = vgbase + (long long)r * SS + c;
            *(uint4*)(smem + FLV_H + r * 272 + c * 2) = *(const uint4*)&vthp[o];
            *(uint4*)(smem + FLV_L + r * 272 + c * 2) = *(const uint4*)&vtlp[o];
        }
        if (tid < 32)
            *(int4*)(smem + FLMASK + tid * 16) = *(const int4*)&maskp[b * SS + kt * 128 + tid * 4];
        __syncthreads();

        // ---- S = Q K^T, 3-pass ----
        float sacc[16][4];
        #pragma unroll
        for (int j = 0; j < 16; j++) {
            sacc[j][0] = 0.f; sacc[j][1] = 0.f; sacc[j][2] = 0.f; sacc[j][3] = 0.f;
        }
        #pragma unroll
        for (int ks = 0; ks < 4; ks++) {
            #pragma unroll
            for (int pg = 0; pg < 8; pg++) {
                uint32_t bh4[4], bl4[4];
                ldsm4(bh4, boffK + pg * 2304 + ks * 32);
                ldsm4(bl4, boffK + 18432 + pg * 2304 + ks * 32);
                mma16816(sacc[2*pg],   qa[ks],  bh4[0], bh4[2]);
                mma16816(sacc[2*pg+1], qa[ks],  bh4[1], bh4[3]);
                mma16816(sacc[2*pg],   qa[ks],  bl4[0], bl4[2]);
                mma16816(sacc[2*pg+1], qa[ks],  bl4[1], bl4[3]);
                mma16816(sacc[2*pg],   qla[ks], bh4[0], bh4[2]);
                mma16816(sacc[2*pg+1], qla[ks], bh4[1], bh4[3]);
            }
        }
        // ---- scale + mask ----
        #pragma unroll
        for (int j = 0; j < 16; j++) {
            int2 mk = *(const int2*)(smem + FLMASK + (j * 8 + (lane & 3) * 2) * 4);
            sacc[j][0] = mk.x ? sacc[j][0] * 0.125f : NEGV;
            sacc[j][1] = mk.y ? sacc[j][1] * 0.125f : NEGV;
            sacc[j][2] = mk.x ? sacc[j][2] * 0.125f : NEGV;
            sacc[j][3] = mk.y ? sacc[j][3] * 0.125f : NEGV;
        }
        // ---- online softmax ----
        float mt0 = NEGV, mt1 = NEGV;
        #pragma unroll
        for (int j = 0; j < 16; j++) {
            mt0 = fmaxf(mt0, fmaxf(sacc[j][0], sacc[j][1]));
            mt1 = fmaxf(mt1, fmaxf(sacc[j][2], sacc[j][3]));
        }
        mt0 = fmaxf(mt0, __shfl_xor_sync(0xffffffffu, mt0, 1));
        mt0 = fmaxf(mt0, __shfl_xor_sync(0xffffffffu, mt0, 2));
        mt1 = fmaxf(mt1, __shfl_xor_sync(0xffffffffu, mt1, 1));
        mt1 = fmaxf(mt1, __shfl_xor_sync(0xffffffffu, mt1, 2));
        float mn0 = fmaxf(mold0, mt0), mn1 = fmaxf(mold1, mt1);
        float sc0 = __expf(mold0 - mn0), sc1 = __expf(mold1 - mn1);
        float rs0 = 0.f, rs1 = 0.f;
        #pragma unroll
        for (int j = 0; j < 16; j++) {
            sacc[j][0] = __expf(sacc[j][0] - mn0);
            sacc[j][1] = __expf(sacc[j][1] - mn0);
            sacc[j][2] = __expf(sacc[j][2] - mn1);
            sacc[j][3] = __expf(sacc[j][3] - mn1);
            rs0 += sacc[j][0] + sacc[j][1];
            rs1 += sacc[j][2] + sacc[j][3];
        }
        rs0 += __shfl_xor_sync(0xffffffffu, rs0, 1);
        rs0 += __shfl_xor_sync(0xffffffffu, rs0, 2);
        rs1 += __shfl_xor_sync(0xffffffffu, rs1, 1);
        rs1 += __shfl_xor_sync(0xffffffffu, rs1, 2);
        lsum0 = lsum0 * sc0 + rs0;
        lsum1 = lsum1 * sc1 + rs1;
        mold0 = mn0; mold1 = mn1;
        #pragma unroll
        for (int j = 0; j < 8; j++) {
            oacc[j][0] *= sc0; oacc[j][1] *= sc0;
            oacc[j][2] *= sc1; oacc[j][3] *= sc1;
        }
        // ---- O += P V : P in regs (fragment reuse), V from smem, 3-pass ----
        #pragma unroll
        for (int t = 0; t < 8; t++) {
            uint32_t ah4[4], al4[4];
            {
                float p0 = sacc[2*t][0],   p1 = sacc[2*t][1];
                float p2 = sacc[2*t][2],   p3 = sacc[2*t][3];
                float p4 = sacc[2*t+1][0], p5 = sacc[2*t+1][1];
                float p6 = sacc[2*t+1][2], p7 = sacc[2*t+1][3];
                ah4[0] = packbf2(p0, p1);
                ah4[1] = packbf2(p2, p3);
                ah4[2] = packbf2(p4, p5);
                ah4[3] = packbf2(p6, p7);
                al4[0] = packbf2(p0 - __uint_as_float(ah4[0] << 16), p1 - __uint_as_float(ah4[0] & 0xffff0000u));
                al4[1] = packbf2(p2 - __uint_as_float(ah4[1] << 16), p3 - __uint_as_float(ah4[1] & 0xffff0000u));
                al4[2] = packbf2(p4 - __uint_as_float(ah4[2] << 16), p5 - __uint_as_float(ah4[2] & 0xffff0000u));
                al4[3] = packbf2(p6 - __uint_as_float(ah4[3] << 16), p7 - __uint_as_float(ah4[3] & 0xffff0000u));
            }
            #pragma unroll
            for (int pg = 0; pg < 4; pg++) {
                uint32_t vh4[4], vl4[4];
                ldsm4(vh4, boffV + pg * 4352 + t * 32);
                ldsm4(vl4, boffV + 17408 + pg * 4352 + t * 32);
                mma16816(oacc[2*pg],   ah4, vh4[0], vh4[2]);
                mma16816(oacc[2*pg+1], ah4, vh4[1], vh4[3]);
                mma16816(oacc[2*pg],   al4, vh4[0], vh4[2]);
                mma16816(oacc[2*pg+1], al4, vh4[1], vh4[3]);
                mma16816(oacc[2*pg],   ah4, vl4[0], vl4[2]);
                mma16816(oacc[2*pg+1], ah4, vl4[1], vl4[3]);
            }
        }
    }

    // ---- epilogue: normalize, split, write cat [B,S,512] ----
    const float li0 = 1.f / lsum0, li1 = 1.f / lsum1;
    const long long row_lo = (long long)b * SS + q0 + w * 16 + (lane >> 2);
    #pragma unroll
    for (int j = 0; j < 8; j++) {
        const int cn = h * 64 + j * 8 + (lane & 3) * 2;
        float v0 = oacc[j][0] * li0, v1 = oacc[j][1] * li0;
        float v2 = oacc[j][2] * li1, v3 = oacc[j][3] * li1;
        bf16 h0,l0,h1,l1;
        split1(v0,h0,l0); split1(v1,h1,l1);
        __nv_bfloat162 hp; hp.x=h0; hp.y=h1;
        __nv_bfloat162 lp; lp.x=l0; lp.y=l1;
        *(__nv_bfloat162*)&cath[row_lo * DD + cn] = hp;
        *(__nv_bfloat162*)&catl[row_lo * DD + cn] = lp;
        split1(v2,h0,l0); split1(v3,h1,l1);
        hp.x=h0; hp.y=h1; lp.x=l0; lp.y=l1;
        *(__nv_bfloat162*)&cath[(row_lo + 8) * DD + cn] = hp;
        *(__nv_bfloat162*)&catl[(row_lo + 8) * DD + cn] = lp;
    }
}

// ---------------- split fp32 -> bf16 hi/lo ----------------
__global__ void __launch_bounds__(256) split_f32(
    const float4* __restrict__ in, bf16* __restrict__ hi, bf16* __restrict__ lo, int n4)
{
    int idx = blockIdx.x * 256 + threadIdx.x;
    if (idx >= n4) return;
    float4 v = in[idx];
    bf16 h0,l0,h1,l1,h2,l2,h3,l3;
    split1(v.x,h0,l0); split1(v.y,h1,l1); split1(v.z,h2,l2); split1(v.w,h3,l3);
    __nv_bfloat162* hp = (__nv_bfloat162*)(hi + (size_t)idx*4);
    __nv_bfloat162* lp = (__nv_bfloat162*)(lo + (size_t)idx*4);
    __nv_bfloat162 a; a.x=h0; a.y=h1; __nv_bfloat162 b; b.x=h2; b.y=h3;
    hp[0]=a; hp[1]=b;
    a.x=l0; a.y=l1; b.x=l2; b.y=l3;
    lp[0]=a; lp[1]=b;
}

// ---------------- weight repack+split: [H,D,DK] -> [N=H*DK, K=D] hi/lo ----------------
__global__ void __launch_bounds__(256) repack_w(
    const float* __restrict__ w, bf16* __restrict__ oh, bf16* __restrict__ ol)
{
    int idx = blockIdx.x * 256 + threadIdx.x;   // over H*D*DK = 2^18
    int j = idx & 63;             // dk
    int d = (idx >> 6) & 511;     // d
    int h = idx >> 15;            // h
    bf16 hi, lo;
    split1(w[idx], hi, lo);
    int o = (h * DKK + j) * DD + d;
    oh[o] = hi; ol[o] = lo;
}

// ---------------- v transpose+split: [B,S,H*64] f32 -> [B,H,64,S] hi/lo ----------------
__global__ void __launch_bounds__(256) transpose_v(
    const float* __restrict__ v, bf16* __restrict__ vth, bf16* __restrict__ vtl)
{
    __shared__ float tile[32][33];
    const int bh = blockIdx.z;
    const int b = bh >> 3, h = bh & 7;
    const int s0 = blockIdx.x * 32, d0 = blockIdx.y * 32;
    const int ty0 = threadIdx.y;            // 0..7
    #pragma unroll
    for (int rs = 0; rs < 4; rs++) {
        int ty = ty0 + rs * 8;
        tile[ty][threadIdx.x] =
            v[((long long)b * SS + s0 + ty) * DD + h * 64 + d0 + threadIdx.x];
    }
    __syncthreads();
    #pragma unroll
    for (int rs = 0; rs < 4; rs++) {
        int ty = ty0 + rs * 8;
        float val = tile[threadIdx.x][ty];
        bf16 hi, lo;
        split1(val, hi, lo);
        long long o = ((long long)bh * 64 + d0 + ty) * SS + s0 + threadIdx.x;
        vth[o] = hi; vtl[o] = lo;
    }
}

// ---------------- LayerNorm over whole [S,D] per batch ----------------
__global__ void __launch_bounds__(256) ln_partial_kernel(
    const float* __restrict__ z, float2* __restrict__ part)
{
    const long long base = (long long)blockIdx.x * 4096;
    const float4* p = (const float4*)(z + base);
    float s = 0.f, q = 0.f;
    for (int i = threadIdx.x; i < 1024; i += 256) {
        float4 v = p[i];
        s += v.x + v.y + v.z + v.w;
        q += v.x*v.x + v.y*v.y + v.z*v.z + v.w*v.w;
    }
    __shared__ float ss[8], sq[8];
    const int lane = threadIdx.x & 31, w = threadIdx.x >> 5;
    #pragma unroll
    for (int o = 16; o; o >>= 1) {
        s += __shfl_xor_sync(0xffffffffu, s, o);
        q += __shfl_xor_sync(0xffffffffu, q, o);
    }
    if (lane == 0) { ss[w] = s; sq[w] = q; }
    __syncthreads();
    if (threadIdx.x == 0) {
        float ts = 0.f, tq = 0.f;
        #pragma unroll
        for (int j = 0; j < 8; j++) { ts += ss[j]; tq += sq[j]; }
        part[blockIdx.x] = make_float2(ts, tq);
    }
}

__global__ void __launch_bounds__(128) ln_final_kernel(
    const float2* __restrict__ part, float2* __restrict__ stats)
{
    float2 v = part[blockIdx.x * 128 + threadIdx.x];
    float s = v.x, q = v.y;
    __shared__ float ss[4], sq[4];
    const int lane = threadIdx.x & 31, w = threadIdx.x >> 5;
    #pragma unroll
    for (int o = 16; o; o >>= 1) {
        s += __shfl_xor_sync(0xffffffffu, s, o);
        q += __shfl_xor_sync(0xffffffffu, q, o);
    }
    if (lane == 0) { ss[w] = s; sq[w] = q; }
    __syncthreads();
    if (threadIdx.x == 0) {
        float ts = 0.f, tq = 0.f;
        #pragma unroll
        for (int j = 0; j < 4; j++) { ts += ss[j]; tq += sq[j]; }
        float mean = ts * (1.f / SD);
        float var = tq * (1.f / SD) - mean * mean;
        stats[blockIdx.x] = make_float2(mean, rsqrtf(var + 1e-6f));
    }
}

template<bool SPLIT>
__global__ void __launch_bounds__(256) ln_apply_kernel(
    const float* __restrict__ z, const float2* __restrict__ stats,
    const float* __restrict__ w, const float* __restrict__ bias,
    float* __restrict__ out, bf16* __restrict__ oh, bf16* __restrict__ ol)
{
    const int idx = blockIdx.x * 256 + threadIdx.x;
    const long long linear = (long long)idx * 4;
    const int b = (int)(linear >> 19);
    const int sd = (int)(linear & (SD - 1));
    float2 st = stats[b];
    float4 v  = ((const float4*)z)[idx];
    float4 wv = ((const float4*)w)[sd >> 2];
    float4 bv = ((const float4*)bias)[sd >> 2];
    float4 o;
    o.x = (v.x - st.x) * st.y * wv.x + bv.x;
    o.y = (v.y - st.x) * st.y * wv.y + bv.y;
    o.z = (v.z - st.x) * st.y * wv.z + bv.z;
    o.w = (v.w - st.x) * st.y * wv.w + bv.w;
    ((float4*)out)[idx] = o;
    if (SPLIT) {
        bf16 h0,l0,h1,l1,h2,l2,h3,l3;
        split1(o.x,h0,l0); split1(o.y,h1,l1); split1(o.z,h2,l2); split1(o.w,h3,l3);
        __nv_bfloat162* hp = (__nv_bfloat162*)(oh + (size_t)idx*4);
        __nv_bfloat162* lp = (__nv_bfloat162*)(ol + (size_t)idx*4);
        __nv_bfloat162 a; a.x=h0; a.y=h1; __nv_bfloat162 c; c.x=h2; c.y=h3;
        hp[0]=a; hp[1]=c;
        a.x=l0; a.y=l1; c.x=l2; c.y=l3;
        lp[0]=a; lp[1]=c;
    }
}

// ---------------- host orchestration ----------------
#define SM128 (2*(20480 + 2*128*80))   // 81920

struct Ptrs {
    bf16 *xh,*xl,*yh,*yl,*qh,*ql,*kh,*kl,*vth,*vtl,*cath,*catl;
    bf16 *x1h,*x1l,*x2h,*x2l,*ffh,*ffl;
    bf16 *wqh,*wql,*wkh,*wkl,*wvh,*wvl,*woh,*wol,*w1h,*w1l,*w2h,*w2l;
    float *v,*z,*x1,*x2;
    float2 *part,*stats;
};

static void run_ln(const float* z, const float* w, const float* b, float* out,
                   bf16* oh, bf16* ol, Ptrs& P)
{
    ln_partial_kernel<<<BB*128, 256>>>(z, P.part);
    ln_final_kernel<<<BB, 128>>>(P.part, P.stats);
    if (oh) ln_apply_kernel<true ><<<(BB*SD)/(256*4), 256>>>(z, P.stats, w, b, out, oh, ol);
    else    ln_apply_kernel<false><<<(BB*SD)/(256*4), 256>>>(z, P.stats, w, b, out, nullptr, nullptr);
}

static void run_mha(const bf16* qinh, const bf16* qinl,
                    const bf16* kinh, const bf16* kinl,
                    const float* wq, const float* bq,
                    const float* wk, const float* bk,
                    const float* wv, const float* bv,
                    const float* wo, const float* bo,
                    const int* mask, const float* resid,
                    Ptrs& P, float* zout)
{
    repack_w<<<1024, 256>>>(wq, P.wqh, P.wql);
    repack_w<<<1024, 256>>>(wk, P.wkh, P.wkl);
    repack_w<<<1024, 256>>>(wv, P.wvh, P.wvl);
    split_f32<<<(DD*DD/4+255)/256, 256>>>((const float4*)wo, P.woh, P.wol, DD*DD/4);

    // projections: [B*S,512] x [512,512]^T
    dim3 gp(DD/128, (BB*SS)/128, 1);
    gemm_mma<128,false,false,true><<<gp,256,SM128>>>(
        qinh, qinl, P.wqh, P.wql, bq, nullptr,
        nullptr, P.qh, P.ql,
        DD, DD, DD, DD, 1,0,1,0, 1,0,1,0, 1,0,1,0, 1.f);
    gemm_mma<128,false,false,true><<<gp,256,SM128>>>(
        kinh, kinl, P.wkh, P.wkl, bk, nullptr,
        nullptr, P.kh, P.kl,
        DD, DD, DD, DD, 1,0,1,0, 1,0,1,0, 1,0,1,0, 1.f);
    gemm_mma<128,false,true,false><<<gp,256,SM128>>>(
        kinh, kinl, P.wvh, P.wvl, bv, nullptr,
        P.v, nullptr, nullptr,
        DD, DD, DD, DD, 1,0,1,0, 1,0,1,0, 1,0,1,0, 1.f);

    transpose_v<<<dim3(SS/32, 2, BB*HH), dim3(32,8)>>>(P.v, P.vth, P.vtl);

    // fused attention: scores + softmax + AV in one kernel
    flash_attn<<<dim3(SS/128, BB*HH), 256, FL_SMEM>>>(
        P.qh, P.ql, P.kh, P.kl, P.vth, P.vtl, mask, P.cath, P.catl);

    // out projection + bias + residual
    dim3 go(DD/128, (BB*SS)/128, 1);
    gemm_mma<128,false,true,false><<<go,256,SM128>>>(
        P.cath, P.catl, P.woh, P.wol, bo, resid,
        zout, nullptr, nullptr,
        DD, DD, DD, DD, 1,0,1,0, 1,0,1,0, 1,0,1,0, 1.f);
}

extern "C" void kernel_launch(void* const* d_in, const int* in_sizes, int n_in,
                              void* d_out, int out_size)
{
    const float* x        = (const float*)d_in[0];
    const float* y        = (const float*)d_in[1];
    const int*   src_mask = (const int*)  d_in[2];
    const int*   trg_mask = (const int*)  d_in[3];
    const float* m1_wq = (const float*)d_in[4];
    const float* m1_bq = (const float*)d_in[5];
    const float* m1_wk = (const float*)d_in[6];
    const float* m1_bk = (const float*)d_in[7];
    const float* m1_wv = (const float*)d_in[8];
    const float* m1_bv = (const float*)d_in[9];
    const float* m1_wo = (const float*)d_in[10];
    const float* m1_bo = (const float*)d_in[11];
    const float* m2_wq = (const float*)d_in[12];
    const float* m2_bq = (const float*)d_in[13];
    const float* m2_wk = (const float*)d_in[14];
    const float* m2_bk = (const float*)d_in[15];
    const float* m2_wv = (const float*)d_in[16];
    const float* m2_bv = (const float*)d_in[17];
    const float* m2_wo = (const float*)d_in[18];
    const float* m2_bo = (const float*)d_in[19];
    const float* pw1   = (const float*)d_in[20];
    const float* pb1   = (const float*)d_in[21];
    const float* pw2   = (const float*)d_in[22];
    const float* pb2   = (const float*)d_in[23];
    const float* ln1_w = (const float*)d_in[24];
    const float* ln1_b = (const float*)d_in[25];
    const float* ln2_w = (const float*)d_in[26];
    const float* ln2_b = (const float*)d_in[27];
    const float* ln3_w = (const float*)d_in[28];
    const float* ln3_b = (const float*)d_in[29];
    float* out = (float*)d_out;

    Ptrs P;
    cudaGetSymbolAddress((void**)&P.xh, g_xh);   cudaGetSymbolAddress((void**)&P.xl, g_xl);
    cudaGetSymbolAddress((void**)&P.yh, g_yh);   cudaGetSymbolAddress((void**)&P.yl, g_yl);
    cudaGetSymbolAddress((void**)&P.qh, g_qh);   cudaGetSymbolAddress((void**)&P.ql, g_ql);
    cudaGetSymbolAddress((void**)&P.kh, g_kh);   cudaGetSymbolAddress((void**)&P.kl, g_kl);
    cudaGetSymbolAddress((void**)&P.vth, g_vth); cudaGetSymbolAddress((void**)&P.vtl, g_vtl);
    cudaGetSymbolAddress((void**)&P.cath, g_cath); cudaGetSymbolAddress((void**)&P.catl, g_catl);
    cudaGetSymbolAddress((void**)&P.x1h, g_x1h); cudaGetSymbolAddress((void**)&P.x1l, g_x1l);
    cudaGetSymbolAddress((void**)&P.x2h, g_x2h); cudaGetSymbolAddress((void**)&P.x2l, g_x2l);
    cudaGetSymbolAddress((void**)&P.ffh, g_ffh); cudaGetSymbolAddress((void**)&P.ffl, g_ffl);
    cudaGetSymbolAddress((void**)&P.wqh, g_wqh); cudaGetSymbolAddress((void**)&P.wql, g_wql);
    cudaGetSymbolAddress((void**)&P.wkh, g_wkh); cudaGetSymbolAddress((void**)&P.wkl, g_wkl);
    cudaGetSymbolAddress((void**)&P.wvh, g_wvh); cudaGetSymbolAddress((void**)&P.wvl, g_wvl);
    cudaGetSymbolAddress((void**)&P.woh, g_woh); cudaGetSymbolAddress((void**)&P.wol, g_wol);
    cudaGetSymbolAddress((void**)&P.w1h, g_w1h); cudaGetSymbolAddress((void**)&P.w1l, g_w1l);
    cudaGetSymbolAddress((void**)&P.w2h, g_w2h); cudaGetSymbolAddress((void**)&P.w2l, g_w2l);
    cudaGetSymbolAddress((void**)&P.v, g_v);
    cudaGetSymbolAddress((void**)&P.z, g_z);
    cudaGetSymbolAddress((void**)&P.x1, g_x1);
    cudaGetSymbolAddress((void**)&P.x2, g_x2);
    cudaGetSymbolAddress((void**)&P.part, g_part);
    cudaGetSymbolAddress((void**)&P.stats, g_stats);

    cudaFuncSetAttribute(gemm_mma<128,false,false,true>, cudaFuncAttributeMaxDynamicSharedMemorySize, SM128);
    cudaFuncSetAttribute(gemm_mma<128,false,true,false>, cudaFuncAttributeMaxDynamicSharedMemorySize, SM128);
    cudaFuncSetAttribute(gemm_mma<128,true ,false,true>, cudaFuncAttributeMaxDynamicSharedMemorySize, SM128);
    cudaFuncSetAttribute(flash_attn, cudaFuncAttributeMaxDynamicSharedMemorySize, FL_SMEM);

    // split inputs once
    split_f32<<<(BB*SD/4+255)/256, 256>>>((const float4*)x, P.xh, P.xl, BB*SD/4);
    split_f32<<<(BB*SD/4+255)/256, 256>>>((const float4*)y, P.yh, P.yl, BB*SD/4);
    split_f32<<<(DFFF*DD/4+255)/256, 256>>>((const float4*)pw1, P.w1h, P.w1l, DFFF*DD/4);
    split_f32<<<(DD*DFFF/4+255)/256, 256>>>((const float4*)pw2, P.w2h, P.w2l, DD*DFFF/4);

    // 1) self-attention (trg_mask) + residual, LN1 -> x1 (+split)
    run_mha(P.xh, P.xl, P.xh, P.xl,
            m1_wq, m1_bq, m1_wk, m1_bk, m1_wv, m1_bv, m1_wo, m1_bo,
            trg_mask, x, P, P.z);
    run_ln(P.z, ln1_w, ln1_b, P.x1, P.x1h, P.x1l, P);

    // 2) cross-attention (q from x1, k/v from y; src_mask) + residual, LN2 -> x2 (+split)
    run_mha(P.x1h, P.x1l, P.yh, P.yl,
            m2_wq, m2_bq, m2_wk, m2_bk, m2_wv, m2_bv, m2_wo, m2_bo,
            src_mask, P.x1, P, P.z);
    run_ln(P.z, ln2_w, ln2_b, P.x2, P.x2h, P.x2l, P);

    // 3) FFN + residual, LN3 -> out
    dim3 gf1(DFFF/128, (BB*SS)/128, 1);
    gemm_mma<128,true,false,true><<<gf1,256,SM128>>>(
        P.x2h, P.x2l, P.w1h, P.w1l, pb1, nullptr,
        nullptr, P.ffh, P.ffl,
        DD, DD, DD, DFFF, 1,0,1,0, 1,0,1,0, 1,0,1,0, 1.f);
    dim3 gf2(DD/128, (BB*SS)/128, 1);
    gemm_mma<128,false,true,false><<<gf2,256,SM128>>>(
        P.ffh, P.ffl, P.w2h, P.w2l, pb2, P.x2,
        P.z, nullptr, nullptr,
        DFFF, DFFF, DFFF, DD, 1,0,1,0, 1,0,1,0, 1,0,1,0, 1.f);
    run_ln(P.z, ln3_w, ln3_b, out, nullptr, nullptr, P);
}